// round 1
// baseline (speedup 1.0000x reference)
#include <cuda_runtime.h>
#include <cuda_bf16.h>
#include <math.h>

// Problem constants
#define BB 2
#define SS 2048
#define HID 2048
#define NH 32
#define NKV 4
#define DD 64
#define N_REP 8
#define MROWS (BB * SS)           // 4096
#define QSCALE 0.125f             // D^-0.5
#define EPS 1e-6f

// ---------------- scratch (static device memory; no allocations allowed) ----
__device__ float d_qbuf[(size_t)MROWS * NH * DD];     // [B,S,NH,D]
__device__ float d_kbuf[(size_t)MROWS * NKV * DD];    // [B,S,NKV,D]
__device__ float d_vbuf[(size_t)MROWS * NKV * DD];    // [B,S,NKV,D]
__device__ float d_gbuf[(size_t)MROWS * NH * DD];     // gate [B,S,2048]
__device__ float d_abuf[(size_t)MROWS * NH * DD];     // attention out [B,S,2048]

// ---------------- SGEMM: C[m,n] = sum_k A[m,k] * B[n,k]  (both K-major) -----
// 128x128 tile, BK=8, 256 threads, 8x8 microtile per thread.
__global__ __launch_bounds__(256, 2) void sgemm_nt(
    const float* __restrict__ A, const float* __restrict__ B,
    float* __restrict__ C, int M, int N, int K)
{
    __shared__ float As[8][128];
    __shared__ float Bs[8][128];

    const int bm = blockIdx.y * 128;
    const int bn = blockIdx.x * 128;
    const int tid = threadIdx.x;
    const int ty = tid >> 4;         // 0..15
    const int tx = tid & 15;         // 0..15
    const int lr = tid >> 1;         // 0..127
    const int lc = (tid & 1) << 2;   // 0 or 4

    const float* Ap = A + (size_t)(bm + lr) * K + lc;
    const float* Bp = B + (size_t)(bn + lr) * K + lc;

    float acc[8][8];
#pragma unroll
    for (int i = 0; i < 8; i++)
#pragma unroll
        for (int j = 0; j < 8; j++) acc[i][j] = 0.f;

    for (int k0 = 0; k0 < K; k0 += 8) {
        float4 a4 = *(const float4*)(Ap + k0);
        float4 b4 = *(const float4*)(Bp + k0);
        As[lc + 0][lr] = a4.x; As[lc + 1][lr] = a4.y;
        As[lc + 2][lr] = a4.z; As[lc + 3][lr] = a4.w;
        Bs[lc + 0][lr] = b4.x; Bs[lc + 1][lr] = b4.y;
        Bs[lc + 2][lr] = b4.z; Bs[lc + 3][lr] = b4.w;
        __syncthreads();
#pragma unroll
        for (int kk = 0; kk < 8; kk++) {
            float4 a0 = *(const float4*)&As[kk][ty * 8];
            float4 a1 = *(const float4*)&As[kk][ty * 8 + 4];
            float4 b0 = *(const float4*)&Bs[kk][tx * 8];
            float4 b1 = *(const float4*)&Bs[kk][tx * 8 + 4];
            float ar[8] = {a0.x, a0.y, a0.z, a0.w, a1.x, a1.y, a1.z, a1.w};
            float br[8] = {b0.x, b0.y, b0.z, b0.w, b1.x, b1.y, b1.z, b1.w};
#pragma unroll
            for (int i = 0; i < 8; i++)
#pragma unroll
                for (int j = 0; j < 8; j++) acc[i][j] = fmaf(ar[i], br[j], acc[i][j]);
        }
        __syncthreads();
    }
#pragma unroll
    for (int i = 0; i < 8; i++) {
        float* Crow = C + (size_t)(bm + ty * 8 + i) * N + bn + tx * 8;
        *(float4*)(Crow)     = make_float4(acc[i][0], acc[i][1], acc[i][2], acc[i][3]);
        *(float4*)(Crow + 4) = make_float4(acc[i][4], acc[i][5], acc[i][6], acc[i][7]);
    }
}

// ---------------- per-head RMSNorm + RoPE (in place) ------------------------
// One warp per (b,s,head) row of D=64. lane handles d=lane and d=lane+32.
__global__ __launch_bounds__(256) void norm_rope(
    float* __restrict__ X, const float* __restrict__ cosb,
    const float* __restrict__ sinb, const float* __restrict__ gamma,
    int nheads, int total_rows)
{
    int warp = (blockIdx.x * 256 + threadIdx.x) >> 5;
    int lane = threadIdx.x & 31;
    if (warp >= total_rows) return;
    int bs = warp / nheads;           // b*S + s
    float* x = X + (size_t)warp * DD;
    float v0 = x[lane];
    float v1 = x[lane + 32];
    float ss = v0 * v0 + v1 * v1;
#pragma unroll
    for (int o = 16; o > 0; o >>= 1) ss += __shfl_xor_sync(0xffffffffu, ss, o);
    float inv = rsqrtf(ss * (1.0f / DD) + EPS);
    float n0 = v0 * inv * gamma[lane];
    float n1 = v1 * inv * gamma[lane + 32];
    const float* cp = cosb + (size_t)bs * DD;
    const float* sp = sinb + (size_t)bs * DD;
    float c0 = cp[lane],      s0 = sp[lane];
    float c1 = cp[lane + 32], s1 = sp[lane + 32];
    // rotate_half: rot[d] = -x[d+32] (d<32) ; x[d-32] (d>=32)
    x[lane]      = n0 * c0 - n1 * s0;
    x[lane + 32] = n1 * c1 + n0 * s1;
}

// ---------------- flash attention + fused gate ------------------------------
// Block: 256 threads (16x16), one (b, h, 64-query tile).
// smem: Qt[d][q] 64x68, Kt[d][k] 64x68 (reused as P[q][k] stride 68), V[k][d] 64x68
#define APAD 68
#define SMEM_ATTN (3 * 64 * APAD * 4)

__global__ __launch_bounds__(256) void attn_kernel(
    float* __restrict__ Out)
{
    extern __shared__ float sm[];
    float* sQt = sm;                    // [64][68] d-major
    float* sKt = sm + 64 * APAD;        // [64][68] d-major; reused as P row-major
    float* sV  = sm + 2 * 64 * APAD;    // [64][68] row=k, col=d

    const int qt = blockIdx.x;
    const int h  = blockIdx.y;
    const int b  = blockIdx.z;
    const int kvh = h / N_REP;
    const int tid = threadIdx.x;
    const int ty = tid >> 4;   // 0..15 -> query rows ty*4..+3
    const int tx = tid & 15;   // 0..15 -> cols tx*4..+3

    // ---- load Q tile (scaled), store transposed [d][q]
    const float* Qb = d_qbuf + (((size_t)(b * SS) + qt * 64) * NH + h) * DD;
#pragma unroll 4
    for (int i = tid; i < 1024; i += 256) {
        int r = i >> 4;
        int c4 = (i & 15) << 2;
        float4 q4 = *(const float4*)(Qb + (size_t)r * (NH * DD) + c4);
        sQt[(c4 + 0) * APAD + r] = q4.x * QSCALE;
        sQt[(c4 + 1) * APAD + r] = q4.y * QSCALE;
        sQt[(c4 + 2) * APAD + r] = q4.z * QSCALE;
        sQt[(c4 + 3) * APAD + r] = q4.w * QSCALE;
    }

    float m_i[4], l_i[4], o[4][4];
#pragma unroll
    for (int i = 0; i < 4; i++) {
        m_i[i] = -1e30f; l_i[i] = 0.f;
#pragma unroll
        for (int j = 0; j < 4; j++) o[i][j] = 0.f;
    }
    __syncthreads();

    for (int kt = 0; kt < SS / 64; kt++) {
        // ---- load K (transposed) and V (row-major) tiles
        const float* Kb = d_kbuf + (((size_t)(b * SS) + kt * 64) * NKV + kvh) * DD;
        const float* Vb = d_vbuf + (((size_t)(b * SS) + kt * 64) * NKV + kvh) * DD;
#pragma unroll 4
        for (int i = tid; i < 1024; i += 256) {
            int r = i >> 4;
            int c4 = (i & 15) << 2;
            float4 k4 = *(const float4*)(Kb + (size_t)r * (NKV * DD) + c4);
            sKt[(c4 + 0) * APAD + r] = k4.x;
            sKt[(c4 + 1) * APAD + r] = k4.y;
            sKt[(c4 + 2) * APAD + r] = k4.z;
            sKt[(c4 + 3) * APAD + r] = k4.w;
            float4 v4 = *(const float4*)(Vb + (size_t)r * (NKV * DD) + c4);
            *(float4*)(sV + r * APAD + c4) = v4;
        }
        __syncthreads();

        // ---- S = Q K^T (scaled already)
        float acc[4][4];
#pragma unroll
        for (int i = 0; i < 4; i++)
#pragma unroll
            for (int j = 0; j < 4; j++) acc[i][j] = 0.f;
#pragma unroll
        for (int d = 0; d < 64; d++) {
            float4 q4 = *(const float4*)(sQt + d * APAD + (ty << 2));
            float4 k4 = *(const float4*)(sKt + d * APAD + (tx << 2));
            float qa[4] = {q4.x, q4.y, q4.z, q4.w};
            float ka[4] = {k4.x, k4.y, k4.z, k4.w};
#pragma unroll
            for (int i = 0; i < 4; i++)
#pragma unroll
                for (int j = 0; j < 4; j++) acc[i][j] = fmaf(qa[i], ka[j], acc[i][j]);
        }

        // ---- online softmax (rows reduced across the 16 lanes sharing ty)
#pragma unroll
        for (int i = 0; i < 4; i++) {
            float rmax = fmaxf(fmaxf(acc[i][0], acc[i][1]), fmaxf(acc[i][2], acc[i][3]));
#pragma unroll
            for (int off = 1; off < 16; off <<= 1)
                rmax = fmaxf(rmax, __shfl_xor_sync(0xffffffffu, rmax, off));
            float m_new = fmaxf(m_i[i], rmax);
            float alpha = __expf(m_i[i] - m_new);
            m_i[i] = m_new;
            float su = 0.f;
#pragma unroll
            for (int j = 0; j < 4; j++) {
                float p = __expf(acc[i][j] - m_new);
                acc[i][j] = p;
                su += p;
            }
#pragma unroll
            for (int off = 1; off < 16; off <<= 1)
                su += __shfl_xor_sync(0xffffffffu, su, off);
            l_i[i] = l_i[i] * alpha + su;
#pragma unroll
            for (int j = 0; j < 4; j++) o[i][j] *= alpha;
        }

        // ---- write P into sKt (reuse) then O += P V
        __syncthreads();
#pragma unroll
        for (int i = 0; i < 4; i++)
            *(float4*)(sKt + (ty * 4 + i) * APAD + (tx << 2)) =
                make_float4(acc[i][0], acc[i][1], acc[i][2], acc[i][3]);
        __syncthreads();

#pragma unroll
        for (int k4 = 0; k4 < 16; k4++) {
            float4 p4[4];
#pragma unroll
            for (int i = 0; i < 4; i++)
                p4[i] = *(const float4*)(sKt + (ty * 4 + i) * APAD + k4 * 4);
            float4 vr[4];
#pragma unroll
            for (int u = 0; u < 4; u++)
                vr[u] = *(const float4*)(sV + (k4 * 4 + u) * APAD + (tx << 2));
#pragma unroll
            for (int i = 0; i < 4; i++) {
                o[i][0] = fmaf(p4[i].x, vr[0].x, o[i][0]);
                o[i][1] = fmaf(p4[i].x, vr[0].y, o[i][1]);
                o[i][2] = fmaf(p4[i].x, vr[0].z, o[i][2]);
                o[i][3] = fmaf(p4[i].x, vr[0].w, o[i][3]);
                o[i][0] = fmaf(p4[i].y, vr[1].x, o[i][0]);
                o[i][1] = fmaf(p4[i].y, vr[1].y, o[i][1]);
                o[i][2] = fmaf(p4[i].y, vr[1].z, o[i][2]);
                o[i][3] = fmaf(p4[i].y, vr[1].w, o[i][3]);
                o[i][0] = fmaf(p4[i].z, vr[2].x, o[i][0]);
                o[i][1] = fmaf(p4[i].z, vr[2].y, o[i][1]);
                o[i][2] = fmaf(p4[i].z, vr[2].z, o[i][2]);
                o[i][3] = fmaf(p4[i].z, vr[2].w, o[i][3]);
                o[i][0] = fmaf(p4[i].w, vr[3].x, o[i][0]);
                o[i][1] = fmaf(p4[i].w, vr[3].y, o[i][1]);
                o[i][2] = fmaf(p4[i].w, vr[3].z, o[i][2]);
                o[i][3] = fmaf(p4[i].w, vr[3].w, o[i][3]);
            }
        }
        __syncthreads();
    }

    // ---- normalize, gate with sigmoid, store to [B,S,NH*D]
    const size_t obase = ((size_t)(b * SS) + qt * 64) * (NH * DD) + h * DD;
#pragma unroll
    for (int i = 0; i < 4; i++) {
        int qrow = ty * 4 + i;
        float inv = 1.f / l_i[i];
        const float* gp = d_gbuf + obase + (size_t)qrow * (NH * DD) + (tx << 2);
        float4 g = *(const float4*)gp;
        float4 r;
        r.x = o[i][0] * inv * (1.f / (1.f + __expf(-g.x)));
        r.y = o[i][1] * inv * (1.f / (1.f + __expf(-g.y)));
        r.z = o[i][2] * inv * (1.f / (1.f + __expf(-g.z)));
        r.w = o[i][3] * inv * (1.f / (1.f + __expf(-g.w)));
        *(float4*)(d_abuf + obase + (size_t)qrow * (NH * DD) + (tx << 2)) = r;
    }
}

// ---------------- launch -----------------------------------------------------
extern "C" void kernel_launch(void* const* d_in, const int* in_sizes, int n_in,
                              void* d_out, int out_size)
{
    const float* hs   = (const float*)d_in[0];
    const float* cosb = (const float*)d_in[1];
    const float* sinb = (const float*)d_in[2];
    const float* Wq   = (const float*)d_in[3];
    const float* Wk   = (const float*)d_in[4];
    const float* Wv   = (const float*)d_in[5];
    const float* Wg   = (const float*)d_in[6];
    const float* Wo   = (const float*)d_in[7];
    const float* qg   = (const float*)d_in[8];
    const float* kg   = (const float*)d_in[9];
    float* out = (float*)d_out;

    float *qbuf, *kbuf, *vbuf, *gbuf, *abuf;
    cudaGetSymbolAddress((void**)&qbuf, d_qbuf);
    cudaGetSymbolAddress((void**)&kbuf, d_kbuf);
    cudaGetSymbolAddress((void**)&vbuf, d_vbuf);
    cudaGetSymbolAddress((void**)&gbuf, d_gbuf);
    cudaGetSymbolAddress((void**)&abuf, d_abuf);

    // Projections
    sgemm_nt<<<dim3(16, 32), 256>>>(hs, Wq, qbuf, MROWS, NH * DD, HID);
    sgemm_nt<<<dim3(2, 32), 256>>>(hs, Wk, kbuf, MROWS, NKV * DD, HID);
    sgemm_nt<<<dim3(2, 32), 256>>>(hs, Wv, vbuf, MROWS, NKV * DD, HID);
    sgemm_nt<<<dim3(16, 32), 256>>>(hs, Wg, gbuf, MROWS, NH * DD, HID);

    // RMSNorm + RoPE on q and k
    {
        int rows_q = MROWS * NH;
        int rows_k = MROWS * NKV;
        norm_rope<<<(rows_q * 32 + 255) / 256, 256>>>(qbuf, cosb, sinb, qg, NH, rows_q);
        norm_rope<<<(rows_k * 32 + 255) / 256, 256>>>(kbuf, cosb, sinb, kg, NKV, rows_k);
    }

    // Attention (+ fused sigmoid gate)
    cudaFuncSetAttribute(attn_kernel, cudaFuncAttributeMaxDynamicSharedMemorySize, SMEM_ATTN);
    attn_kernel<<<dim3(SS / 64, NH, BB), 256, SMEM_ATTN>>>(abuf);

    // Output projection
    sgemm_nt<<<dim3(16, 32), 256>>>(abuf, Wo, out, MROWS, HID, HID);
}

// round 3
// speedup vs baseline: 1.6294x; 1.6294x over previous
#include <cuda_runtime.h>
#include <cuda_bf16.h>
#include <math.h>
#include <cstdint>

// Problem constants
#define BB 2
#define SS 2048
#define HID 2048
#define NH 32
#define NKV 4
#define DD 64
#define N_REP 8
#define MROWS (BB * SS)           // 4096
#define QSCALE 0.125f             // D^-0.5
#define EPS 1e-6f

// ---------------- async copy helpers ----------------------------------------
#define CP_ASYNC16(smem_u32, gptr) \
    asm volatile("cp.async.cg.shared.global [%0], [%1], 16;" :: "r"(smem_u32), "l"(gptr))
#define CP_COMMIT() asm volatile("cp.async.commit_group;" ::: "memory")
#define CP_WAIT1()  asm volatile("cp.async.wait_group 1;" ::: "memory")
#define CP_WAIT0()  asm volatile("cp.async.wait_group 0;" ::: "memory")

__device__ __forceinline__ uint32_t smem_u32(const void* p) {
    uint32_t a;
    asm("{ .reg .u64 t; cvta.to.shared.u64 t, %1; cvt.u32.u64 %0, t; }" : "=r"(a) : "l"(p));
    return a;
}
__device__ __forceinline__ void ldsm_x4(uint32_t& r0, uint32_t& r1, uint32_t& r2, uint32_t& r3,
                                        uint32_t addr) {
    asm volatile("ldmatrix.sync.aligned.m8n8.x4.shared.b16 {%0,%1,%2,%3}, [%4];"
                 : "=r"(r0), "=r"(r1), "=r"(r2), "=r"(r3) : "r"(addr));
}
__device__ __forceinline__ void mma16816(float& c0, float& c1, float& c2, float& c3,
                                         uint32_t a0, uint32_t a1, uint32_t a2, uint32_t a3,
                                         uint32_t b0, uint32_t b1) {
    asm volatile(
        "mma.sync.aligned.m16n8k16.row.col.f32.bf16.bf16.f32 "
        "{%0,%1,%2,%3}, {%4,%5,%6,%7}, {%8,%9}, {%0,%1,%2,%3};"
        : "+f"(c0), "+f"(c1), "+f"(c2), "+f"(c3)
        : "r"(a0), "r"(a1), "r"(a2), "r"(a3), "r"(b0), "r"(b1));
}

// ---------------- scratch (static device memory) ----------------------------
__device__ float d_qbuf[(size_t)MROWS * NH * DD];
__device__ float d_kbuf[(size_t)MROWS * NKV * DD];
__device__ float d_vbuf[(size_t)MROWS * NKV * DD];
__device__ float d_gbuf[(size_t)MROWS * NH * DD];
__device__ float d_abuf[(size_t)MROWS * NH * DD];

__device__ __nv_bfloat16 g_hs_h[(size_t)MROWS * HID];
__device__ __nv_bfloat16 g_hs_l[(size_t)MROWS * HID];
__device__ __nv_bfloat16 g_wq_h[(size_t)NH * DD * HID];
__device__ __nv_bfloat16 g_wq_l[(size_t)NH * DD * HID];
__device__ __nv_bfloat16 g_wk_h[(size_t)NKV * DD * HID];
__device__ __nv_bfloat16 g_wk_l[(size_t)NKV * DD * HID];
__device__ __nv_bfloat16 g_wv_h[(size_t)NKV * DD * HID];
__device__ __nv_bfloat16 g_wv_l[(size_t)NKV * DD * HID];
__device__ __nv_bfloat16 g_wg_h[(size_t)NH * DD * HID];
__device__ __nv_bfloat16 g_wg_l[(size_t)NH * DD * HID];
__device__ __nv_bfloat16 g_wo_h[(size_t)HID * HID];
__device__ __nv_bfloat16 g_wo_l[(size_t)HID * HID];
__device__ __nv_bfloat16 g_ab_h[(size_t)MROWS * HID];
__device__ __nv_bfloat16 g_ab_l[(size_t)MROWS * HID];

// ---------------- split fp32 -> bf16 hi/lo ----------------------------------
__global__ __launch_bounds__(256) void split_bf16(
    const float* __restrict__ X, __nv_bfloat16* __restrict__ hi,
    __nv_bfloat16* __restrict__ lo, int n4)
{
    int i = blockIdx.x * 256 + threadIdx.x;
    if (i >= n4) return;
    float4 x = ((const float4*)X)[i];
    __nv_bfloat16 h0 = __float2bfloat16(x.x);
    __nv_bfloat16 h1 = __float2bfloat16(x.y);
    __nv_bfloat16 h2 = __float2bfloat16(x.z);
    __nv_bfloat16 h3 = __float2bfloat16(x.w);
    __nv_bfloat16 l0 = __float2bfloat16(x.x - __bfloat162float(h0));
    __nv_bfloat16 l1 = __float2bfloat16(x.y - __bfloat162float(h1));
    __nv_bfloat16 l2 = __float2bfloat16(x.z - __bfloat162float(h2));
    __nv_bfloat16 l3 = __float2bfloat16(x.w - __bfloat162float(h3));
    ((__nv_bfloat162*)hi)[2*i]     = __nv_bfloat162(h0, h1);
    ((__nv_bfloat162*)hi)[2*i + 1] = __nv_bfloat162(h2, h3);
    ((__nv_bfloat162*)lo)[2*i]     = __nv_bfloat162(l0, l1);
    ((__nv_bfloat162*)lo)[2*i + 1] = __nv_bfloat162(l2, l3);
}

// ---------------- HMMA bf16x3 GEMM ------------------------------------------
// C[m,n] = sum_k A[m,k]*B[n,k] over 3 passes (AhBh + AhBl + AlBh), fp32 accum.
// CTA 128x128, BK=64, 8 warps of 32x64 (m16n8k16).
#define GPAD 72                    // smem row stride in bf16 elements
#define TILE_BYTES (128 * GPAD * 2)   // 18432 per matrix
#define STAGE_BYTES (2 * TILE_BYTES)  // A + B
#define GEMM_SMEM (2 * STAGE_BYTES)   // double buffer: 73728

__global__ __launch_bounds__(256) void gemm_bf16x3(
    const __nv_bfloat16* __restrict__ Ah, const __nv_bfloat16* __restrict__ Al,
    const __nv_bfloat16* __restrict__ Bh, const __nv_bfloat16* __restrict__ Bl,
    float* __restrict__ C, int M, int N, int K)
{
    extern __shared__ char smem[];
    const uint32_t sbase = smem_u32(smem);
    const int tid = threadIdx.x;
    const int wid = tid >> 5;
    const int lane = tid & 31;
    const int wm = wid & 3;        // 0..3 -> 32-row group
    const int wn = wid >> 2;       // 0..1 -> 64-col group
    const int bm = blockIdx.y * 128;
    const int bn = blockIdx.x * 128;

    const int nchunk = K >> 6;
    const int total = 3 * nchunk;
    const __nv_bfloat16* APtr[3] = {Ah, Ah, Al};
    const __nv_bfloat16* BPtr[3] = {Bh, Bl, Bh};

    // per-thread load mapping: 4 chunks of 16B per matrix per stage
    const int lrow = tid >> 3;          // 0..31 (+32 per u)
    const int lcol = (tid & 7) * 8;     // bf16 col

    // ldmatrix lane address offsets
    const int g = lane >> 3, li = lane & 7;
    const int a_row = (g & 1) * 8 + li;       // within 16-row tile
    const int a_kof = (g >> 1) * 8;           // 0 or 8
    const int b_nof = (g >> 1) * 8 + li;      // within 16-col (n) pair
    const int b_kof = (g & 1) * 8;            // 0 or 8

    float acc[2][8][4];
#pragma unroll
    for (int mt = 0; mt < 2; mt++)
#pragma unroll
        for (int nt = 0; nt < 8; nt++)
#pragma unroll
            for (int r = 0; r < 4; r++) acc[mt][nt][r] = 0.f;

    auto load_stage = [&](int s, int idx) {
        const __nv_bfloat16* A = APtr[idx / nchunk];
        const __nv_bfloat16* B = BPtr[idx / nchunk];
        const int k0 = (idx % nchunk) << 6;
        const uint32_t sA = sbase + s * STAGE_BYTES;
        const uint32_t sB = sA + TILE_BYTES;
#pragma unroll
        for (int u = 0; u < 4; u++) {
            int row = lrow + u * 32;
            uint32_t so = (uint32_t)(row * GPAD + lcol) * 2;
            CP_ASYNC16(sA + so, A + (size_t)(bm + row) * K + k0 + lcol);
            CP_ASYNC16(sB + so, B + (size_t)(bn + row) * K + k0 + lcol);
        }
        CP_COMMIT();
    };

    load_stage(0, 0);

    for (int i = 0; i < total; i++) {
        const int s = i & 1;
        if (i + 1 < total) { load_stage(s ^ 1, i + 1); CP_WAIT1(); }
        else               { CP_WAIT0(); }
        __syncthreads();

        const uint32_t sA = sbase + s * STAGE_BYTES;
        const uint32_t sB = sA + TILE_BYTES;
        // base lane addresses for this stage
        uint32_t aAddr0 = sA + (uint32_t)((wm * 32 + a_row) * GPAD + a_kof) * 2;
        uint32_t aAddr1 = aAddr0 + (uint32_t)(16 * GPAD) * 2;
        uint32_t bAddr[4];
#pragma unroll
        for (int p = 0; p < 4; p++)
            bAddr[p] = sB + (uint32_t)((wn * 64 + p * 16 + b_nof) * GPAD + b_kof) * 2;

#pragma unroll
        for (int ks = 0; ks < 4; ks++) {
            const uint32_t ko = ks * 32;   // 16 bf16 = 32 bytes per k-step
            uint32_t a0[4], a1[4];
            ldsm_x4(a0[0], a0[1], a0[2], a0[3], aAddr0 + ko);
            ldsm_x4(a1[0], a1[1], a1[2], a1[3], aAddr1 + ko);
            uint32_t br[4][4];
#pragma unroll
            for (int p = 0; p < 4; p++)
                ldsm_x4(br[p][0], br[p][1], br[p][2], br[p][3], bAddr[p] + ko);
#pragma unroll
            for (int nt = 0; nt < 8; nt++) {
                const int p = nt >> 1, h = nt & 1;
                uint32_t b0 = br[p][h * 2], b1 = br[p][h * 2 + 1];
                mma16816(acc[0][nt][0], acc[0][nt][1], acc[0][nt][2], acc[0][nt][3],
                         a0[0], a0[1], a0[2], a0[3], b0, b1);
                mma16816(acc[1][nt][0], acc[1][nt][1], acc[1][nt][2], acc[1][nt][3],
                         a1[0], a1[1], a1[2], a1[3], b0, b1);
            }
        }
        __syncthreads();
    }

    // epilogue: direct global stores (float2 pairs)
    const int crow = lane >> 2;
    const int ccol = (lane & 3) * 2;
#pragma unroll
    for (int mt = 0; mt < 2; mt++) {
        int m0 = bm + wm * 32 + mt * 16 + crow;
#pragma unroll
        for (int nt = 0; nt < 8; nt++) {
            int n0 = bn + wn * 64 + nt * 8 + ccol;
            *(float2*)(C + (size_t)m0 * N + n0)       = make_float2(acc[mt][nt][0], acc[mt][nt][1]);
            *(float2*)(C + (size_t)(m0 + 8) * N + n0) = make_float2(acc[mt][nt][2], acc[mt][nt][3]);
        }
    }
}

// ---------------- per-head RMSNorm + RoPE (in place) ------------------------
__global__ __launch_bounds__(256) void norm_rope(
    float* __restrict__ X, const float* __restrict__ cosb,
    const float* __restrict__ sinb, const float* __restrict__ gamma,
    int nheads, int total_rows)
{
    int warp = (blockIdx.x * 256 + threadIdx.x) >> 5;
    int lane = threadIdx.x & 31;
    if (warp >= total_rows) return;
    int bs = warp / nheads;
    float* x = X + (size_t)warp * DD;
    float v0 = x[lane];
    float v1 = x[lane + 32];
    float ss = v0 * v0 + v1 * v1;
#pragma unroll
    for (int o = 16; o > 0; o >>= 1) ss += __shfl_xor_sync(0xffffffffu, ss, o);
    float inv = rsqrtf(ss * (1.0f / DD) + EPS);
    float n0 = v0 * inv * gamma[lane];
    float n1 = v1 * inv * gamma[lane + 32];
    const float* cp = cosb + (size_t)bs * DD;
    const float* sp = sinb + (size_t)bs * DD;
    x[lane]      = n0 * cp[lane]      - n1 * sp[lane];
    x[lane + 32] = n1 * cp[lane + 32] + n0 * sp[lane + 32];
}

// ---------------- flash attention + fused gate (fp32) ------------------------
#define APAD 68
#define SMEM_ATTN (3 * 64 * APAD * 4)

__global__ __launch_bounds__(256) void attn_kernel(float* __restrict__ Out)
{
    extern __shared__ float sm[];
    float* sQt = sm;
    float* sKt = sm + 64 * APAD;
    float* sV  = sm + 2 * 64 * APAD;

    const int qt = blockIdx.x;
    const int h  = blockIdx.y;
    const int b  = blockIdx.z;
    const int kvh = h / N_REP;
    const int tid = threadIdx.x;
    const int ty = tid >> 4;
    const int tx = tid & 15;

    const float* Qb = d_qbuf + (((size_t)(b * SS) + qt * 64) * NH + h) * DD;
#pragma unroll 4
    for (int i = tid; i < 1024; i += 256) {
        int r = i >> 4;
        int c4 = (i & 15) << 2;
        float4 q4 = *(const float4*)(Qb + (size_t)r * (NH * DD) + c4);
        sQt[(c4 + 0) * APAD + r] = q4.x * QSCALE;
        sQt[(c4 + 1) * APAD + r] = q4.y * QSCALE;
        sQt[(c4 + 2) * APAD + r] = q4.z * QSCALE;
        sQt[(c4 + 3) * APAD + r] = q4.w * QSCALE;
    }

    float m_i[4], l_i[4], o[4][4];
#pragma unroll
    for (int i = 0; i < 4; i++) {
        m_i[i] = -1e30f; l_i[i] = 0.f;
#pragma unroll
        for (int j = 0; j < 4; j++) o[i][j] = 0.f;
    }
    __syncthreads();

    for (int kt = 0; kt < SS / 64; kt++) {
        const float* Kb = d_kbuf + (((size_t)(b * SS) + kt * 64) * NKV + kvh) * DD;
        const float* Vb = d_vbuf + (((size_t)(b * SS) + kt * 64) * NKV + kvh) * DD;
#pragma unroll 4
        for (int i = tid; i < 1024; i += 256) {
            int r = i >> 4;
            int c4 = (i & 15) << 2;
            float4 k4 = *(const float4*)(Kb + (size_t)r * (NKV * DD) + c4);
            sKt[(c4 + 0) * APAD + r] = k4.x;
            sKt[(c4 + 1) * APAD + r] = k4.y;
            sKt[(c4 + 2) * APAD + r] = k4.z;
            sKt[(c4 + 3) * APAD + r] = k4.w;
            float4 v4 = *(const float4*)(Vb + (size_t)r * (NKV * DD) + c4);
            *(float4*)(sV + r * APAD + c4) = v4;
        }
        __syncthreads();

        float acc[4][4];
#pragma unroll
        for (int i = 0; i < 4; i++)
#pragma unroll
            for (int j = 0; j < 4; j++) acc[i][j] = 0.f;
#pragma unroll
        for (int d = 0; d < 64; d++) {
            float4 q4 = *(const float4*)(sQt + d * APAD + (ty << 2));
            float4 k4 = *(const float4*)(sKt + d * APAD + (tx << 2));
            float qa[4] = {q4.x, q4.y, q4.z, q4.w};
            float ka[4] = {k4.x, k4.y, k4.z, k4.w};
#pragma unroll
            for (int i = 0; i < 4; i++)
#pragma unroll
                for (int j = 0; j < 4; j++) acc[i][j] = fmaf(qa[i], ka[j], acc[i][j]);
        }

#pragma unroll
        for (int i = 0; i < 4; i++) {
            float rmax = fmaxf(fmaxf(acc[i][0], acc[i][1]), fmaxf(acc[i][2], acc[i][3]));
#pragma unroll
            for (int off = 1; off < 16; off <<= 1)
                rmax = fmaxf(rmax, __shfl_xor_sync(0xffffffffu, rmax, off));
            float m_new = fmaxf(m_i[i], rmax);
            float alpha = __expf(m_i[i] - m_new);
            m_i[i] = m_new;
            float su = 0.f;
#pragma unroll
            for (int j = 0; j < 4; j++) {
                float p = __expf(acc[i][j] - m_new);
                acc[i][j] = p;
                su += p;
            }
#pragma unroll
            for (int off = 1; off < 16; off <<= 1)
                su += __shfl_xor_sync(0xffffffffu, su, off);
            l_i[i] = l_i[i] * alpha + su;
#pragma unroll
            for (int j = 0; j < 4; j++) o[i][j] *= alpha;
        }

        __syncthreads();
#pragma unroll
        for (int i = 0; i < 4; i++)
            *(float4*)(sKt + (ty * 4 + i) * APAD + (tx << 2)) =
                make_float4(acc[i][0], acc[i][1], acc[i][2], acc[i][3]);
        __syncthreads();

#pragma unroll
        for (int k4 = 0; k4 < 16; k4++) {
            float4 p4[4];
#pragma unroll
            for (int i = 0; i < 4; i++)
                p4[i] = *(const float4*)(sKt + (ty * 4 + i) * APAD + k4 * 4);
            float4 vr[4];
#pragma unroll
            for (int u = 0; u < 4; u++)
                vr[u] = *(const float4*)(sV + (k4 * 4 + u) * APAD + (tx << 2));
#pragma unroll
            for (int i = 0; i < 4; i++) {
                o[i][0] = fmaf(p4[i].x, vr[0].x, o[i][0]);
                o[i][1] = fmaf(p4[i].x, vr[0].y, o[i][1]);
                o[i][2] = fmaf(p4[i].x, vr[0].z, o[i][2]);
                o[i][3] = fmaf(p4[i].x, vr[0].w, o[i][3]);
                o[i][0] = fmaf(p4[i].y, vr[1].x, o[i][0]);
                o[i][1] = fmaf(p4[i].y, vr[1].y, o[i][1]);
                o[i][2] = fmaf(p4[i].y, vr[1].z, o[i][2]);
                o[i][3] = fmaf(p4[i].y, vr[1].w, o[i][3]);
                o[i][0] = fmaf(p4[i].z, vr[2].x, o[i][0]);
                o[i][1] = fmaf(p4[i].z, vr[2].y, o[i][1]);
                o[i][2] = fmaf(p4[i].z, vr[2].z, o[i][2]);
                o[i][3] = fmaf(p4[i].z, vr[2].w, o[i][3]);
                o[i][0] = fmaf(p4[i].w, vr[3].x, o[i][0]);
                o[i][1] = fmaf(p4[i].w, vr[3].y, o[i][1]);
                o[i][2] = fmaf(p4[i].w, vr[3].z, o[i][2]);
                o[i][3] = fmaf(p4[i].w, vr[3].w, o[i][3]);
            }
        }
        __syncthreads();
    }

    const size_t obase = ((size_t)(b * SS) + qt * 64) * (NH * DD) + h * DD;
#pragma unroll
    for (int i = 0; i < 4; i++) {
        int qrow = ty * 4 + i;
        float inv = 1.f / l_i[i];
        const float* gp = d_gbuf + obase + (size_t)qrow * (NH * DD) + (tx << 2);
        float4 g4 = *(const float4*)gp;
        float4 r;
        r.x = o[i][0] * inv * (1.f / (1.f + __expf(-g4.x)));
        r.y = o[i][1] * inv * (1.f / (1.f + __expf(-g4.y)));
        r.z = o[i][2] * inv * (1.f / (1.f + __expf(-g4.z)));
        r.w = o[i][3] * inv * (1.f / (1.f + __expf(-g4.w)));
        *(float4*)(d_abuf + obase + (size_t)qrow * (NH * DD) + (tx << 2)) = r;
    }
}

// ---------------- launch -----------------------------------------------------
extern "C" void kernel_launch(void* const* d_in, const int* in_sizes, int n_in,
                              void* d_out, int out_size)
{
    const float* hs   = (const float*)d_in[0];
    const float* cosb = (const float*)d_in[1];
    const float* sinb = (const float*)d_in[2];
    const float* Wq   = (const float*)d_in[3];
    const float* Wk   = (const float*)d_in[4];
    const float* Wv   = (const float*)d_in[5];
    const float* Wg   = (const float*)d_in[6];
    const float* Wo   = (const float*)d_in[7];
    const float* qg   = (const float*)d_in[8];
    const float* kg   = (const float*)d_in[9];
    float* out = (float*)d_out;

    float *qbuf, *kbuf, *vbuf, *gbuf, *abuf;
    cudaGetSymbolAddress((void**)&qbuf, d_qbuf);
    cudaGetSymbolAddress((void**)&kbuf, d_kbuf);
    cudaGetSymbolAddress((void**)&vbuf, d_vbuf);
    cudaGetSymbolAddress((void**)&gbuf, d_gbuf);
    cudaGetSymbolAddress((void**)&abuf, d_abuf);

    __nv_bfloat16 *hs_h, *hs_l, *wq_h, *wq_l, *wk_h, *wk_l, *wv_h, *wv_l;
    __nv_bfloat16 *wg_h, *wg_l, *wo_h, *wo_l, *ab_h, *ab_l;
    cudaGetSymbolAddress((void**)&hs_h, g_hs_h);
    cudaGetSymbolAddress((void**)&hs_l, g_hs_l);
    cudaGetSymbolAddress((void**)&wq_h, g_wq_h);
    cudaGetSymbolAddress((void**)&wq_l, g_wq_l);
    cudaGetSymbolAddress((void**)&wk_h, g_wk_h);
    cudaGetSymbolAddress((void**)&wk_l, g_wk_l);
    cudaGetSymbolAddress((void**)&wv_h, g_wv_h);
    cudaGetSymbolAddress((void**)&wv_l, g_wv_l);
    cudaGetSymbolAddress((void**)&wg_h, g_wg_h);
    cudaGetSymbolAddress((void**)&wg_l, g_wg_l);
    cudaGetSymbolAddress((void**)&wo_h, g_wo_h);
    cudaGetSymbolAddress((void**)&wo_l, g_wo_l);
    cudaGetSymbolAddress((void**)&ab_h, g_ab_h);
    cudaGetSymbolAddress((void**)&ab_l, g_ab_l);

    cudaFuncSetAttribute(gemm_bf16x3, cudaFuncAttributeMaxDynamicSharedMemorySize, GEMM_SMEM);
    cudaFuncSetAttribute(attn_kernel, cudaFuncAttributeMaxDynamicSharedMemorySize, SMEM_ATTN);

    // splits
    {
        int n4;
        n4 = MROWS * HID / 4;      split_bf16<<<(n4 + 255) / 256, 256>>>(hs, hs_h, hs_l, n4);
        n4 = NH * DD * HID / 4;    split_bf16<<<(n4 + 255) / 256, 256>>>(Wq, wq_h, wq_l, n4);
        n4 = NKV * DD * HID / 4;   split_bf16<<<(n4 + 255) / 256, 256>>>(Wk, wk_h, wk_l, n4);
        n4 = NKV * DD * HID / 4;   split_bf16<<<(n4 + 255) / 256, 256>>>(Wv, wv_h, wv_l, n4);
        n4 = NH * DD * HID / 4;    split_bf16<<<(n4 + 255) / 256, 256>>>(Wg, wg_h, wg_l, n4);
        n4 = HID * HID / 4;        split_bf16<<<(n4 + 255) / 256, 256>>>(Wo, wo_h, wo_l, n4);
    }

    // projections via HMMA
    gemm_bf16x3<<<dim3(NH * DD / 128, MROWS / 128), 256, GEMM_SMEM>>>(
        hs_h, hs_l, wq_h, wq_l, qbuf, MROWS, NH * DD, HID);
    gemm_bf16x3<<<dim3(NKV * DD / 128, MROWS / 128), 256, GEMM_SMEM>>>(
        hs_h, hs_l, wk_h, wk_l, kbuf, MROWS, NKV * DD, HID);
    gemm_bf16x3<<<dim3(NKV * DD / 128, MROWS / 128), 256, GEMM_SMEM>>>(
        hs_h, hs_l, wv_h, wv_l, vbuf, MROWS, NKV * DD, HID);
    gemm_bf16x3<<<dim3(NH * DD / 128, MROWS / 128), 256, GEMM_SMEM>>>(
        hs_h, hs_l, wg_h, wg_l, gbuf, MROWS, NH * DD, HID);

    // RMSNorm + RoPE
    {
        int rows_q = MROWS * NH;
        int rows_k = MROWS * NKV;
        norm_rope<<<(rows_q * 32 + 255) / 256, 256>>>(qbuf, cosb, sinb, qg, NH, rows_q);
        norm_rope<<<(rows_k * 32 + 255) / 256, 256>>>(kbuf, cosb, sinb, kg, NKV, rows_k);
    }

    // attention (+ fused sigmoid gate)
    attn_kernel<<<dim3(SS / 64, NH, BB), 256, SMEM_ATTN>>>(abuf);

    // split attention output, then output projection
    {
        int n4 = MROWS * HID / 4;
        split_bf16<<<(n4 + 255) / 256, 256>>>(abuf, ab_h, ab_l, n4);
    }
    gemm_bf16x3<<<dim3(HID / 128, MROWS / 128), 256, GEMM_SMEM>>>(
        ab_h, ab_l, wo_h, wo_l, out, MROWS, HID, HID);
}

// round 5
// speedup vs baseline: 2.3775x; 1.4591x over previous
#include <cuda_runtime.h>
#include <cuda_bf16.h>
#include <math.h>
#include <cstdint>

// Problem constants
#define BB 2
#define SS 2048
#define HID 2048
#define NH 32
#define NKV 4
#define DD 64
#define N_REP 8
#define MROWS (BB * SS)           // 4096
#define QSCALE 0.125f             // D^-0.5
#define EPS 1e-6f

// ---------------- async copy helpers ----------------------------------------
#define CP_ASYNC16(smem_u32a, gptr) \
    asm volatile("cp.async.cg.shared.global [%0], [%1], 16;" :: "r"(smem_u32a), "l"(gptr))
#define CP_COMMIT() asm volatile("cp.async.commit_group;" ::: "memory")
#define CP_WAIT1()  asm volatile("cp.async.wait_group 1;" ::: "memory")
#define CP_WAIT0()  asm volatile("cp.async.wait_group 0;" ::: "memory")

__device__ __forceinline__ uint32_t smem_u32(const void* p) {
    uint32_t a;
    asm("{ .reg .u64 t; cvta.to.shared.u64 t, %1; cvt.u32.u64 %0, t; }" : "=r"(a) : "l"(p));
    return a;
}
__device__ __forceinline__ void ldsm_x4(uint32_t& r0, uint32_t& r1, uint32_t& r2, uint32_t& r3,
                                        uint32_t addr) {
    asm volatile("ldmatrix.sync.aligned.m8n8.x4.shared.b16 {%0,%1,%2,%3}, [%4];"
                 : "=r"(r0), "=r"(r1), "=r"(r2), "=r"(r3) : "r"(addr));
}
__device__ __forceinline__ void mma16816(float& c0, float& c1, float& c2, float& c3,
                                         uint32_t a0, uint32_t a1, uint32_t a2, uint32_t a3,
                                         uint32_t b0, uint32_t b1) {
    asm volatile(
        "mma.sync.aligned.m16n8k16.row.col.f32.bf16.bf16.f32 "
        "{%0,%1,%2,%3}, {%4,%5,%6,%7}, {%8,%9}, {%0,%1,%2,%3};"
        : "+f"(c0), "+f"(c1), "+f"(c2), "+f"(c3)
        : "r"(a0), "r"(a1), "r"(a2), "r"(a3), "r"(b0), "r"(b1));
}
__device__ __forceinline__ uint32_t pack_bf162(float x, float y) {
    __nv_bfloat162 h = __floats2bfloat162_rn(x, y);
    return *reinterpret_cast<uint32_t*>(&h);
}

// ---------------- scratch (static device memory) ----------------------------
__device__ float d_qbuf[(size_t)MROWS * NH * DD];
__device__ float d_kbuf[(size_t)MROWS * NKV * DD];
__device__ float d_vbuf[(size_t)MROWS * NKV * DD];
__device__ float d_gbuf[(size_t)MROWS * NH * DD];
__device__ float d_abuf[(size_t)MROWS * NH * DD];

__device__ __nv_bfloat16 g_hs_h[(size_t)MROWS * HID];
__device__ __nv_bfloat16 g_hs_l[(size_t)MROWS * HID];
__device__ __nv_bfloat16 g_wq_h[(size_t)NH * DD * HID];
__device__ __nv_bfloat16 g_wq_l[(size_t)NH * DD * HID];
__device__ __nv_bfloat16 g_wk_h[(size_t)NKV * DD * HID];
__device__ __nv_bfloat16 g_wk_l[(size_t)NKV * DD * HID];
__device__ __nv_bfloat16 g_wv_h[(size_t)NKV * DD * HID];
__device__ __nv_bfloat16 g_wv_l[(size_t)NKV * DD * HID];
__device__ __nv_bfloat16 g_wg_h[(size_t)NH * DD * HID];
__device__ __nv_bfloat16 g_wg_l[(size_t)NH * DD * HID];
__device__ __nv_bfloat16 g_wo_h[(size_t)HID * HID];
__device__ __nv_bfloat16 g_wo_l[(size_t)HID * HID];
__device__ __nv_bfloat16 g_ab_h[(size_t)MROWS * HID];
__device__ __nv_bfloat16 g_ab_l[(size_t)MROWS * HID];

// ---------------- split fp32 -> bf16 hi/lo ----------------------------------
__global__ __launch_bounds__(256) void split_bf16(
    const float* __restrict__ X, __nv_bfloat16* __restrict__ hi,
    __nv_bfloat16* __restrict__ lo, int n4)
{
    int i = blockIdx.x * 256 + threadIdx.x;
    if (i >= n4) return;
    float4 x = ((const float4*)X)[i];
    __nv_bfloat16 h0 = __float2bfloat16(x.x);
    __nv_bfloat16 h1 = __float2bfloat16(x.y);
    __nv_bfloat16 h2 = __float2bfloat16(x.z);
    __nv_bfloat16 h3 = __float2bfloat16(x.w);
    __nv_bfloat16 l0 = __float2bfloat16(x.x - __bfloat162float(h0));
    __nv_bfloat16 l1 = __float2bfloat16(x.y - __bfloat162float(h1));
    __nv_bfloat16 l2 = __float2bfloat16(x.z - __bfloat162float(h2));
    __nv_bfloat16 l3 = __float2bfloat16(x.w - __bfloat162float(h3));
    ((__nv_bfloat162*)hi)[2*i]     = __nv_bfloat162(h0, h1);
    ((__nv_bfloat162*)hi)[2*i + 1] = __nv_bfloat162(h2, h3);
    ((__nv_bfloat162*)lo)[2*i]     = __nv_bfloat162(l0, l1);
    ((__nv_bfloat162*)lo)[2*i + 1] = __nv_bfloat162(l2, l3);
}

// ---------------- HMMA bf16x3 GEMM (unchanged from R3) -----------------------
#define GPAD 72
#define TILE_BYTES (128 * GPAD * 2)
#define STAGE_BYTES (2 * TILE_BYTES)
#define GEMM_SMEM (2 * STAGE_BYTES)

__global__ __launch_bounds__(256) void gemm_bf16x3(
    const __nv_bfloat16* __restrict__ Ah, const __nv_bfloat16* __restrict__ Al,
    const __nv_bfloat16* __restrict__ Bh, const __nv_bfloat16* __restrict__ Bl,
    float* __restrict__ C, int M, int N, int K)
{
    extern __shared__ char smem[];
    const uint32_t sbase = smem_u32(smem);
    const int tid = threadIdx.x;
    const int wid = tid >> 5;
    const int lane = tid & 31;
    const int wm = wid & 3;
    const int wn = wid >> 2;
    const int bm = blockIdx.y * 128;
    const int bn = blockIdx.x * 128;

    const int nchunk = K >> 6;
    const int total = 3 * nchunk;
    const __nv_bfloat16* APtr[3] = {Ah, Ah, Al};
    const __nv_bfloat16* BPtr[3] = {Bh, Bl, Bh};

    const int lrow = tid >> 3;
    const int lcol = (tid & 7) * 8;

    const int g = lane >> 3, li = lane & 7;
    const int a_row = (g & 1) * 8 + li;
    const int a_kof = (g >> 1) * 8;
    const int b_nof = (g >> 1) * 8 + li;
    const int b_kof = (g & 1) * 8;

    float acc[2][8][4];
#pragma unroll
    for (int mt = 0; mt < 2; mt++)
#pragma unroll
        for (int nt = 0; nt < 8; nt++)
#pragma unroll
            for (int r = 0; r < 4; r++) acc[mt][nt][r] = 0.f;

    auto load_stage = [&](int s, int idx) {
        const __nv_bfloat16* A = APtr[idx / nchunk];
        const __nv_bfloat16* B = BPtr[idx / nchunk];
        const int k0 = (idx % nchunk) << 6;
        const uint32_t sA = sbase + s * STAGE_BYTES;
        const uint32_t sB = sA + TILE_BYTES;
#pragma unroll
        for (int u = 0; u < 4; u++) {
            int row = lrow + u * 32;
            uint32_t so = (uint32_t)(row * GPAD + lcol) * 2;
            CP_ASYNC16(sA + so, A + (size_t)(bm + row) * K + k0 + lcol);
            CP_ASYNC16(sB + so, B + (size_t)(bn + row) * K + k0 + lcol);
        }
        CP_COMMIT();
    };

    load_stage(0, 0);

    for (int i = 0; i < total; i++) {
        const int s = i & 1;
        if (i + 1 < total) { load_stage(s ^ 1, i + 1); CP_WAIT1(); }
        else               { CP_WAIT0(); }
        __syncthreads();

        const uint32_t sA = sbase + s * STAGE_BYTES;
        const uint32_t sB = sA + TILE_BYTES;
        uint32_t aAddr0 = sA + (uint32_t)((wm * 32 + a_row) * GPAD + a_kof) * 2;
        uint32_t aAddr1 = aAddr0 + (uint32_t)(16 * GPAD) * 2;
        uint32_t bAddr[4];
#pragma unroll
        for (int p = 0; p < 4; p++)
            bAddr[p] = sB + (uint32_t)((wn * 64 + p * 16 + b_nof) * GPAD + b_kof) * 2;

#pragma unroll
        for (int ks = 0; ks < 4; ks++) {
            const uint32_t ko = ks * 32;
            uint32_t a0[4], a1[4];
            ldsm_x4(a0[0], a0[1], a0[2], a0[3], aAddr0 + ko);
            ldsm_x4(a1[0], a1[1], a1[2], a1[3], aAddr1 + ko);
            uint32_t br[4][4];
#pragma unroll
            for (int p = 0; p < 4; p++)
                ldsm_x4(br[p][0], br[p][1], br[p][2], br[p][3], bAddr[p] + ko);
#pragma unroll
            for (int nt = 0; nt < 8; nt++) {
                const int p = nt >> 1, h = nt & 1;
                uint32_t b0 = br[p][h * 2], b1 = br[p][h * 2 + 1];
                mma16816(acc[0][nt][0], acc[0][nt][1], acc[0][nt][2], acc[0][nt][3],
                         a0[0], a0[1], a0[2], a0[3], b0, b1);
                mma16816(acc[1][nt][0], acc[1][nt][1], acc[1][nt][2], acc[1][nt][3],
                         a1[0], a1[1], a1[2], a1[3], b0, b1);
            }
        }
        __syncthreads();
    }

    const int crow = lane >> 2;
    const int ccol = (lane & 3) * 2;
#pragma unroll
    for (int mt = 0; mt < 2; mt++) {
        int m0 = bm + wm * 32 + mt * 16 + crow;
#pragma unroll
        for (int nt = 0; nt < 8; nt++) {
            int n0 = bn + wn * 64 + nt * 8 + ccol;
            *(float2*)(C + (size_t)m0 * N + n0)       = make_float2(acc[mt][nt][0], acc[mt][nt][1]);
            *(float2*)(C + (size_t)(m0 + 8) * N + n0) = make_float2(acc[mt][nt][2], acc[mt][nt][3]);
        }
    }
}

// ---------------- per-head RMSNorm + RoPE (in place) ------------------------
__global__ __launch_bounds__(256) void norm_rope(
    float* __restrict__ X, const float* __restrict__ cosb,
    const float* __restrict__ sinb, const float* __restrict__ gamma,
    int nheads, int total_rows)
{
    int warp = (blockIdx.x * 256 + threadIdx.x) >> 5;
    int lane = threadIdx.x & 31;
    if (warp >= total_rows) return;
    int bs = warp / nheads;
    float* x = X + (size_t)warp * DD;
    float v0 = x[lane];
    float v1 = x[lane + 32];
    float ss = v0 * v0 + v1 * v1;
#pragma unroll
    for (int o = 16; o > 0; o >>= 1) ss += __shfl_xor_sync(0xffffffffu, ss, o);
    float inv = rsqrtf(ss * (1.0f / DD) + EPS);
    float n0 = v0 * inv * gamma[lane];
    float n1 = v1 * inv * gamma[lane + 32];
    const float* cp = cosb + (size_t)bs * DD;
    const float* sp = sinb + (size_t)bs * DD;
    x[lane]      = n0 * cp[lane]      - n1 * sp[lane];
    x[lane + 32] = n1 * cp[lane + 32] + n0 * sp[lane + 32];
}

// ---------------- HMMA flash attention + fused gate -------------------------
// CTA: (qtile 128, head, batch). 8 warps x m16. KV tiles of 64.
// S = QK^T via 3-pass bf16 hi/lo; O = Ph*Vh + Pl*Vh + Ph*Vl.
#define ATPAD 72
#define ATT_SMEM (4 * 64 * ATPAD * 2)   // 36864 B

__global__ __launch_bounds__(256) void attn_hmma()
{
    extern __shared__ __nv_bfloat16 sb[];
    __nv_bfloat16* sKh = sb;                    // [64][72] row=kv col=d
    __nv_bfloat16* sKl = sb + 64 * ATPAD;
    __nv_bfloat16* sVh = sb + 2 * 64 * ATPAD;   // [64][72] row=d col=kv (transposed)
    __nv_bfloat16* sVl = sb + 3 * 64 * ATPAD;

    const int qt = blockIdx.x;
    const int h  = blockIdx.y;
    const int b  = blockIdx.z;
    const int kvh = h >> 3;
    const int tid = threadIdx.x;
    const int wid = tid >> 5;
    const int lane = tid & 31;
    const int g = lane >> 3, li = lane & 7;
    const int a_row = (g & 1) * 8 + li;
    const int a_kof = (g >> 1) * 8;
    const int b_nof = (g >> 1) * 8 + li;
    const int b_kof = (g & 1) * 8;

    // ---- stage Q (fp32 -> scaled bf16 hi/lo) and grab fragments
    {
        const float* Qb = d_qbuf + (((size_t)(b * SS) + qt * 128) * NH + h) * DD;
        __nv_bfloat16* stQh = sKh;   // 128 rows x 72 (spans sKh+sKl)
        __nv_bfloat16* stQl = sVh;   // 128 rows x 72 (spans sVh+sVl)
#pragma unroll
        for (int i = tid; i < 2048; i += 256) {
            int r = i >> 4;
            int c4 = (i & 15) << 2;
            float4 q = *(const float4*)(Qb + (size_t)r * (NH * DD) + c4);
            float v[4] = {q.x * QSCALE, q.y * QSCALE, q.z * QSCALE, q.w * QSCALE};
#pragma unroll
            for (int u = 0; u < 4; u++) {
                __nv_bfloat16 hh = __float2bfloat16(v[u]);
                stQh[r * ATPAD + c4 + u] = hh;
                stQl[r * ATPAD + c4 + u] = __float2bfloat16(v[u] - __bfloat162float(hh));
            }
        }
        __syncthreads();
    }
    uint32_t qh[4][4], ql[4][4];
#pragma unroll
    for (int ks = 0; ks < 4; ks++) {
        uint32_t ah = smem_u32(sKh + (size_t)(wid * 16 + a_row) * ATPAD + ks * 16 + a_kof);
        ldsm_x4(qh[ks][0], qh[ks][1], qh[ks][2], qh[ks][3], ah);
        uint32_t al = smem_u32(sVh + (size_t)(wid * 16 + a_row) * ATPAD + ks * 16 + a_kof);
        ldsm_x4(ql[ks][0], ql[ks][1], ql[ks][2], ql[ks][3], al);
    }
    __syncthreads();

    float O[8][4];
#pragma unroll
    for (int j = 0; j < 8; j++)
#pragma unroll
        for (int r = 0; r < 4; r++) O[j][r] = 0.f;
    float m0 = -1e30f, m1 = -1e30f, l0 = 0.f, l1 = 0.f;

    for (int kt = 0; kt < SS / 64; kt++) {
        // ---- load K,V fp32 -> bf16 hi/lo smem (V transposed)
        const float* Kb = d_kbuf + (((size_t)(b * SS) + kt * 64) * NKV + kvh) * DD;
        const float* Vb = d_vbuf + (((size_t)(b * SS) + kt * 64) * NKV + kvh) * DD;
#pragma unroll
        for (int i = tid; i < 1024; i += 256) {
            int r = i >> 4;
            int c4 = (i & 15) << 2;
            float4 k4 = *(const float4*)(Kb + (size_t)r * (NKV * DD) + c4);
            float kv4[4] = {k4.x, k4.y, k4.z, k4.w};
#pragma unroll
            for (int u = 0; u < 4; u++) {
                __nv_bfloat16 hh = __float2bfloat16(kv4[u]);
                sKh[r * ATPAD + c4 + u] = hh;
                sKl[r * ATPAD + c4 + u] = __float2bfloat16(kv4[u] - __bfloat162float(hh));
            }
            float4 v4 = *(const float4*)(Vb + (size_t)r * (NKV * DD) + c4);
            float vv4[4] = {v4.x, v4.y, v4.z, v4.w};
#pragma unroll
            for (int u = 0; u < 4; u++) {
                __nv_bfloat16 hh = __float2bfloat16(vv4[u]);
                sVh[(c4 + u) * ATPAD + r] = hh;
                sVl[(c4 + u) * ATPAD + r] = __float2bfloat16(vv4[u] - __bfloat162float(hh));
            }
        }
        __syncthreads();

        // ---- S = QK^T (3 passes, fp32 accum)
        float sa[8][4];
#pragma unroll
        for (int j = 0; j < 8; j++)
#pragma unroll
            for (int r = 0; r < 4; r++) sa[j][r] = 0.f;
#pragma unroll
        for (int ks = 0; ks < 4; ks++) {
            uint32_t kb4[4][4];
#pragma unroll
            for (int p = 0; p < 4; p++)
                ldsm_x4(kb4[p][0], kb4[p][1], kb4[p][2], kb4[p][3],
                        smem_u32(sKh + (size_t)(p * 16 + b_nof) * ATPAD + ks * 16 + b_kof));
#pragma unroll
            for (int j = 0; j < 8; j++) {
                const int p = j >> 1, hh = j & 1;
                mma16816(sa[j][0], sa[j][1], sa[j][2], sa[j][3],
                         qh[ks][0], qh[ks][1], qh[ks][2], qh[ks][3],
                         kb4[p][hh * 2], kb4[p][hh * 2 + 1]);
                mma16816(sa[j][0], sa[j][1], sa[j][2], sa[j][3],
                         ql[ks][0], ql[ks][1], ql[ks][2], ql[ks][3],
                         kb4[p][hh * 2], kb4[p][hh * 2 + 1]);
            }
#pragma unroll
            for (int p = 0; p < 4; p++)
                ldsm_x4(kb4[p][0], kb4[p][1], kb4[p][2], kb4[p][3],
                        smem_u32(sKl + (size_t)(p * 16 + b_nof) * ATPAD + ks * 16 + b_kof));
#pragma unroll
            for (int j = 0; j < 8; j++) {
                const int p = j >> 1, hh = j & 1;
                mma16816(sa[j][0], sa[j][1], sa[j][2], sa[j][3],
                         qh[ks][0], qh[ks][1], qh[ks][2], qh[ks][3],
                         kb4[p][hh * 2], kb4[p][hh * 2 + 1]);
            }
        }

        // ---- online softmax (rows l/4 and l/4+8; reduce across quad lanes)
        float tm0 = -1e30f, tm1 = -1e30f;
#pragma unroll
        for (int j = 0; j < 8; j++) {
            tm0 = fmaxf(tm0, fmaxf(sa[j][0], sa[j][1]));
            tm1 = fmaxf(tm1, fmaxf(sa[j][2], sa[j][3]));
        }
        tm0 = fmaxf(tm0, __shfl_xor_sync(0xffffffffu, tm0, 1));
        tm0 = fmaxf(tm0, __shfl_xor_sync(0xffffffffu, tm0, 2));
        tm1 = fmaxf(tm1, __shfl_xor_sync(0xffffffffu, tm1, 1));
        tm1 = fmaxf(tm1, __shfl_xor_sync(0xffffffffu, tm1, 2));
        float mn0 = fmaxf(m0, tm0), mn1 = fmaxf(m1, tm1);
        float al0 = __expf(m0 - mn0), al1 = __expf(m1 - mn1);
        m0 = mn0; m1 = mn1;
        float ls0 = 0.f, ls1 = 0.f;
#pragma unroll
        for (int j = 0; j < 8; j++) {
            sa[j][0] = __expf(sa[j][0] - m0);
            sa[j][1] = __expf(sa[j][1] - m0);
            sa[j][2] = __expf(sa[j][2] - m1);
            sa[j][3] = __expf(sa[j][3] - m1);
            ls0 += sa[j][0] + sa[j][1];
            ls1 += sa[j][2] + sa[j][3];
        }
        ls0 += __shfl_xor_sync(0xffffffffu, ls0, 1);
        ls0 += __shfl_xor_sync(0xffffffffu, ls0, 2);
        ls1 += __shfl_xor_sync(0xffffffffu, ls1, 1);
        ls1 += __shfl_xor_sync(0xffffffffu, ls1, 2);
        l0 = l0 * al0 + ls0;
        l1 = l1 * al1 + ls1;
#pragma unroll
        for (int j = 0; j < 8; j++) {
            O[j][0] *= al0; O[j][1] *= al0;
            O[j][2] *= al1; O[j][3] *= al1;
        }

        // ---- pack P hi/lo (C-frag -> A-frag layout)
        uint32_t pah[4][4], pal[4][4];
#pragma unroll
        for (int t = 0; t < 4; t++) {
            float e[8] = {sa[2*t][0], sa[2*t][1], sa[2*t][2], sa[2*t][3],
                          sa[2*t+1][0], sa[2*t+1][1], sa[2*t+1][2], sa[2*t+1][3]};
            float hi[8], lo[8];
#pragma unroll
            for (int u = 0; u < 8; u++) {
                hi[u] = __bfloat162float(__float2bfloat16(e[u]));
                lo[u] = e[u] - hi[u];
            }
            pah[t][0] = pack_bf162(hi[0], hi[1]);
            pah[t][1] = pack_bf162(hi[2], hi[3]);
            pah[t][2] = pack_bf162(hi[4], hi[5]);
            pah[t][3] = pack_bf162(hi[6], hi[7]);
            pal[t][0] = pack_bf162(lo[0], lo[1]);
            pal[t][1] = pack_bf162(lo[2], lo[3]);
            pal[t][2] = pack_bf162(lo[4], lo[5]);
            pal[t][3] = pack_bf162(lo[6], lo[7]);
        }

        // ---- O += Ph*Vh + Pl*Vh + Ph*Vl
#pragma unroll
        for (int t = 0; t < 4; t++) {
            uint32_t vb4[4][4];
#pragma unroll
            for (int p = 0; p < 4; p++)
                ldsm_x4(vb4[p][0], vb4[p][1], vb4[p][2], vb4[p][3],
                        smem_u32(sVh + (size_t)(p * 16 + b_nof) * ATPAD + t * 16 + b_kof));
#pragma unroll
            for (int j = 0; j < 8; j++) {
                const int p = j >> 1, hh = j & 1;
                mma16816(O[j][0], O[j][1], O[j][2], O[j][3],
                         pah[t][0], pah[t][1], pah[t][2], pah[t][3],
                         vb4[p][hh * 2], vb4[p][hh * 2 + 1]);
                mma16816(O[j][0], O[j][1], O[j][2], O[j][3],
                         pal[t][0], pal[t][1], pal[t][2], pal[t][3],
                         vb4[p][hh * 2], vb4[p][hh * 2 + 1]);
            }
#pragma unroll
            for (int p = 0; p < 4; p++)
                ldsm_x4(vb4[p][0], vb4[p][1], vb4[p][2], vb4[p][3],
                        smem_u32(sVl + (size_t)(p * 16 + b_nof) * ATPAD + t * 16 + b_kof));
#pragma unroll
            for (int j = 0; j < 8; j++) {
                const int p = j >> 1, hh = j & 1;
                mma16816(O[j][0], O[j][1], O[j][2], O[j][3],
                         pah[t][0], pah[t][1], pah[t][2], pah[t][3],
                         vb4[p][hh * 2], vb4[p][hh * 2 + 1]);
            }
        }
        __syncthreads();
    }

    // ---- epilogue: normalize, gate, store
    float inv0 = 1.f / l0, inv1 = 1.f / l1;
    int r0 = qt * 128 + wid * 16 + (lane >> 2);
    int r1 = r0 + 8;
    size_t base0 = ((size_t)(b * SS) + r0) * (NH * DD) + h * DD + ((lane & 3) << 1);
    size_t base1 = ((size_t)(b * SS) + r1) * (NH * DD) + h * DD + ((lane & 3) << 1);
#pragma unroll
    for (int j = 0; j < 8; j++) {
        float2 gA = *(const float2*)(d_gbuf + base0 + j * 8);
        float2 gB = *(const float2*)(d_gbuf + base1 + j * 8);
        float2 oA, oB;
        oA.x = O[j][0] * inv0 * (1.f / (1.f + __expf(-gA.x)));
        oA.y = O[j][1] * inv0 * (1.f / (1.f + __expf(-gA.y)));
        oB.x = O[j][2] * inv1 * (1.f / (1.f + __expf(-gB.x)));
        oB.y = O[j][3] * inv1 * (1.f / (1.f + __expf(-gB.y)));
        *(float2*)(d_abuf + base0 + j * 8) = oA;
        *(float2*)(d_abuf + base1 + j * 8) = oB;
    }
}

// ---------------- launch -----------------------------------------------------
extern "C" void kernel_launch(void* const* d_in, const int* in_sizes, int n_in,
                              void* d_out, int out_size)
{
    const float* hs   = (const float*)d_in[0];
    const float* cosb = (const float*)d_in[1];
    const float* sinb = (const float*)d_in[2];
    const float* Wq   = (const float*)d_in[3];
    const float* Wk   = (const float*)d_in[4];
    const float* Wv   = (const float*)d_in[5];
    const float* Wg   = (const float*)d_in[6];
    const float* Wo   = (const float*)d_in[7];
    const float* qg   = (const float*)d_in[8];
    const float* kg   = (const float*)d_in[9];
    float* out = (float*)d_out;

    float *qbuf, *kbuf, *vbuf, *gbuf, *abuf;
    cudaGetSymbolAddress((void**)&qbuf, d_qbuf);
    cudaGetSymbolAddress((void**)&kbuf, d_kbuf);
    cudaGetSymbolAddress((void**)&vbuf, d_vbuf);
    cudaGetSymbolAddress((void**)&gbuf, d_gbuf);
    cudaGetSymbolAddress((void**)&abuf, d_abuf);

    __nv_bfloat16 *hs_h, *hs_l, *wq_h, *wq_l, *wk_h, *wk_l, *wv_h, *wv_l;
    __nv_bfloat16 *wg_h, *wg_l, *wo_h, *wo_l, *ab_h, *ab_l;
    cudaGetSymbolAddress((void**)&hs_h, g_hs_h);
    cudaGetSymbolAddress((void**)&hs_l, g_hs_l);
    cudaGetSymbolAddress((void**)&wq_h, g_wq_h);
    cudaGetSymbolAddress((void**)&wq_l, g_wq_l);
    cudaGetSymbolAddress((void**)&wk_h, g_wk_h);
    cudaGetSymbolAddress((void**)&wk_l, g_wk_l);
    cudaGetSymbolAddress((void**)&wv_h, g_wv_h);
    cudaGetSymbolAddress((void**)&wv_l, g_wv_l);
    cudaGetSymbolAddress((void**)&wg_h, g_wg_h);
    cudaGetSymbolAddress((void**)&wg_l, g_wg_l);
    cudaGetSymbolAddress((void**)&wo_h, g_wo_h);
    cudaGetSymbolAddress((void**)&wo_l, g_wo_l);
    cudaGetSymbolAddress((void**)&ab_h, g_ab_h);
    cudaGetSymbolAddress((void**)&ab_l, g_ab_l);

    cudaFuncSetAttribute(gemm_bf16x3, cudaFuncAttributeMaxDynamicSharedMemorySize, GEMM_SMEM);
    cudaFuncSetAttribute(attn_hmma, cudaFuncAttributeMaxDynamicSharedMemorySize, ATT_SMEM);

    // splits
    {
        int n4;
        n4 = MROWS * HID / 4;      split_bf16<<<(n4 + 255) / 256, 256>>>(hs, hs_h, hs_l, n4);
        n4 = NH * DD * HID / 4;    split_bf16<<<(n4 + 255) / 256, 256>>>(Wq, wq_h, wq_l, n4);
        n4 = NKV * DD * HID / 4;   split_bf16<<<(n4 + 255) / 256, 256>>>(Wk, wk_h, wk_l, n4);
        n4 = NKV * DD * HID / 4;   split_bf16<<<(n4 + 255) / 256, 256>>>(Wv, wv_h, wv_l, n4);
        n4 = NH * DD * HID / 4;    split_bf16<<<(n4 + 255) / 256, 256>>>(Wg, wg_h, wg_l, n4);
        n4 = HID * HID / 4;        split_bf16<<<(n4 + 255) / 256, 256>>>(Wo, wo_h, wo_l, n4);
    }

    // projections via HMMA
    gemm_bf16x3<<<dim3(NH * DD / 128, MROWS / 128), 256, GEMM_SMEM>>>(
        hs_h, hs_l, wq_h, wq_l, qbuf, MROWS, NH * DD, HID);
    gemm_bf16x3<<<dim3(NKV * DD / 128, MROWS / 128), 256, GEMM_SMEM>>>(
        hs_h, hs_l, wk_h, wk_l, kbuf, MROWS, NKV * DD, HID);
    gemm_bf16x3<<<dim3(NKV * DD / 128, MROWS / 128), 256, GEMM_SMEM>>>(
        hs_h, hs_l, wv_h, wv_l, vbuf, MROWS, NKV * DD, HID);
    gemm_bf16x3<<<dim3(NH * DD / 128, MROWS / 128), 256, GEMM_SMEM>>>(
        hs_h, hs_l, wg_h, wg_l, gbuf, MROWS, NH * DD, HID);

    // RMSNorm + RoPE
    {
        int rows_q = MROWS * NH;
        int rows_k = MROWS * NKV;
        norm_rope<<<(rows_q * 32 + 255) / 256, 256>>>(qbuf, cosb, sinb, qg, NH, rows_q);
        norm_rope<<<(rows_k * 32 + 255) / 256, 256>>>(kbuf, cosb, sinb, kg, NKV, rows_k);
    }

    // attention (+ fused sigmoid gate) via HMMA
    attn_hmma<<<dim3(SS / 128, NH, BB), 256, ATT_SMEM>>>();

    // split attention output, then output projection
    {
        int n4 = MROWS * HID / 4;
        split_bf16<<<(n4 + 255) / 256, 256>>>(abuf, ab_h, ab_l, n4);
    }
    gemm_bf16x3<<<dim3(HID / 128, MROWS / 128), 256, GEMM_SMEM>>>(
        ab_h, ab_l, wo_h, wo_l, out, MROWS, HID, HID);
}

// round 6
// speedup vs baseline: 2.7411x; 1.1529x over previous
#include <cuda_runtime.h>
#include <cuda_bf16.h>
#include <math.h>
#include <cstdint>

// Problem constants
#define BB 2
#define SS 2048
#define HID 2048
#define NH 32
#define NKV 4
#define DD 64
#define N_REP 8
#define MROWS (BB * SS)           // 4096
#define QSCALE 0.125f             // D^-0.5
#define EPS 1e-6f

// ---------------- async copy helpers ----------------------------------------
#define CP_ASYNC16(smem_u32a, gptr) \
    asm volatile("cp.async.cg.shared.global [%0], [%1], 16;" :: "r"(smem_u32a), "l"(gptr))
#define CP_COMMIT() asm volatile("cp.async.commit_group;" ::: "memory")
#define CP_WAIT1()  asm volatile("cp.async.wait_group 1;" ::: "memory")
#define CP_WAIT0()  asm volatile("cp.async.wait_group 0;" ::: "memory")

__device__ __forceinline__ uint32_t smem_u32(const void* p) {
    uint32_t a;
    asm("{ .reg .u64 t; cvta.to.shared.u64 t, %1; cvt.u32.u64 %0, t; }" : "=r"(a) : "l"(p));
    return a;
}
__device__ __forceinline__ void ldsm_x4(uint32_t& r0, uint32_t& r1, uint32_t& r2, uint32_t& r3,
                                        uint32_t addr) {
    asm volatile("ldmatrix.sync.aligned.m8n8.x4.shared.b16 {%0,%1,%2,%3}, [%4];"
                 : "=r"(r0), "=r"(r1), "=r"(r2), "=r"(r3) : "r"(addr));
}
__device__ __forceinline__ void mma16816(float& c0, float& c1, float& c2, float& c3,
                                         uint32_t a0, uint32_t a1, uint32_t a2, uint32_t a3,
                                         uint32_t b0, uint32_t b1) {
    asm volatile(
        "mma.sync.aligned.m16n8k16.row.col.f32.bf16.bf16.f32 "
        "{%0,%1,%2,%3}, {%4,%5,%6,%7}, {%8,%9}, {%0,%1,%2,%3};"
        : "+f"(c0), "+f"(c1), "+f"(c2), "+f"(c3)
        : "r"(a0), "r"(a1), "r"(a2), "r"(a3), "r"(b0), "r"(b1));
}
__device__ __forceinline__ uint32_t pack_bf162(float x, float y) {
    __nv_bfloat162 h = __floats2bfloat162_rn(x, y);
    return *reinterpret_cast<uint32_t*>(&h);
}

// ---------------- scratch (static device memory) ----------------------------
__device__ float d_qbuf[(size_t)MROWS * NH * DD];
__device__ float d_kbuf[(size_t)MROWS * NKV * DD];
__device__ float d_vbuf[(size_t)MROWS * NKV * DD];
__device__ float d_gbuf[(size_t)MROWS * NH * DD];
__device__ float d_abuf[(size_t)MROWS * NH * DD];

__device__ __nv_bfloat16 g_hs_h[(size_t)MROWS * HID];
__device__ __nv_bfloat16 g_hs_l[(size_t)MROWS * HID];
__device__ __nv_bfloat16 g_wq_h[(size_t)NH * DD * HID];
__device__ __nv_bfloat16 g_wq_l[(size_t)NH * DD * HID];
__device__ __nv_bfloat16 g_wk_h[(size_t)NKV * DD * HID];
__device__ __nv_bfloat16 g_wk_l[(size_t)NKV * DD * HID];
__device__ __nv_bfloat16 g_wv_h[(size_t)NKV * DD * HID];
__device__ __nv_bfloat16 g_wv_l[(size_t)NKV * DD * HID];
__device__ __nv_bfloat16 g_wg_h[(size_t)NH * DD * HID];
__device__ __nv_bfloat16 g_wg_l[(size_t)NH * DD * HID];
__device__ __nv_bfloat16 g_wo_h[(size_t)HID * HID];
__device__ __nv_bfloat16 g_wo_l[(size_t)HID * HID];
__device__ __nv_bfloat16 g_ab_h[(size_t)MROWS * HID];
__device__ __nv_bfloat16 g_ab_l[(size_t)MROWS * HID];

// pre-split attention operands (bf16 hi/lo)
__device__ __nv_bfloat16 g_qh[(size_t)MROWS * NH * DD];
__device__ __nv_bfloat16 g_ql[(size_t)MROWS * NH * DD];
__device__ __nv_bfloat16 g_kh[(size_t)MROWS * NKV * DD];
__device__ __nv_bfloat16 g_kl[(size_t)MROWS * NKV * DD];
__device__ __nv_bfloat16 g_vth[(size_t)MROWS * NKV * DD];  // [b][kvh][d][s]
__device__ __nv_bfloat16 g_vtl[(size_t)MROWS * NKV * DD];

// ---------------- split fp32 -> bf16 hi/lo ----------------------------------
__global__ __launch_bounds__(256) void split_bf16(
    const float* __restrict__ X, __nv_bfloat16* __restrict__ hi,
    __nv_bfloat16* __restrict__ lo, int n4)
{
    int i = blockIdx.x * 256 + threadIdx.x;
    if (i >= n4) return;
    float4 x = ((const float4*)X)[i];
    __nv_bfloat16 h0 = __float2bfloat16(x.x);
    __nv_bfloat16 h1 = __float2bfloat16(x.y);
    __nv_bfloat16 h2 = __float2bfloat16(x.z);
    __nv_bfloat16 h3 = __float2bfloat16(x.w);
    __nv_bfloat16 l0 = __float2bfloat16(x.x - __bfloat162float(h0));
    __nv_bfloat16 l1 = __float2bfloat16(x.y - __bfloat162float(h1));
    __nv_bfloat16 l2 = __float2bfloat16(x.z - __bfloat162float(h2));
    __nv_bfloat16 l3 = __float2bfloat16(x.w - __bfloat162float(h3));
    ((__nv_bfloat162*)hi)[2*i]     = __nv_bfloat162(h0, h1);
    ((__nv_bfloat162*)hi)[2*i + 1] = __nv_bfloat162(h2, h3);
    ((__nv_bfloat162*)lo)[2*i]     = __nv_bfloat162(l0, l1);
    ((__nv_bfloat162*)lo)[2*i + 1] = __nv_bfloat162(l2, l3);
}

// ---------------- HMMA bf16x3 GEMM (unchanged, verified) ---------------------
#define GPAD 72
#define TILE_BYTES (128 * GPAD * 2)
#define STAGE_BYTES (2 * TILE_BYTES)
#define GEMM_SMEM (2 * STAGE_BYTES)

__global__ __launch_bounds__(256) void gemm_bf16x3(
    const __nv_bfloat16* __restrict__ Ah, const __nv_bfloat16* __restrict__ Al,
    const __nv_bfloat16* __restrict__ Bh, const __nv_bfloat16* __restrict__ Bl,
    float* __restrict__ C, int M, int N, int K)
{
    extern __shared__ char smem[];
    const uint32_t sbase = smem_u32(smem);
    const int tid = threadIdx.x;
    const int wid = tid >> 5;
    const int lane = tid & 31;
    const int wm = wid & 3;
    const int wn = wid >> 2;
    const int bm = blockIdx.y * 128;
    const int bn = blockIdx.x * 128;

    const int nchunk = K >> 6;
    const int total = 3 * nchunk;
    const __nv_bfloat16* APtr[3] = {Ah, Ah, Al};
    const __nv_bfloat16* BPtr[3] = {Bh, Bl, Bh};

    const int lrow = tid >> 3;
    const int lcol = (tid & 7) * 8;

    const int g = lane >> 3, li = lane & 7;
    const int a_row = (g & 1) * 8 + li;
    const int a_kof = (g >> 1) * 8;
    const int b_nof = (g >> 1) * 8 + li;
    const int b_kof = (g & 1) * 8;

    float acc[2][8][4];
#pragma unroll
    for (int mt = 0; mt < 2; mt++)
#pragma unroll
        for (int nt = 0; nt < 8; nt++)
#pragma unroll
            for (int r = 0; r < 4; r++) acc[mt][nt][r] = 0.f;

    auto load_stage = [&](int s, int idx) {
        const __nv_bfloat16* A = APtr[idx / nchunk];
        const __nv_bfloat16* B = BPtr[idx / nchunk];
        const int k0 = (idx % nchunk) << 6;
        const uint32_t sA = sbase + s * STAGE_BYTES;
        const uint32_t sB = sA + TILE_BYTES;
#pragma unroll
        for (int u = 0; u < 4; u++) {
            int row = lrow + u * 32;
            uint32_t so = (uint32_t)(row * GPAD + lcol) * 2;
            CP_ASYNC16(sA + so, A + (size_t)(bm + row) * K + k0 + lcol);
            CP_ASYNC16(sB + so, B + (size_t)(bn + row) * K + k0 + lcol);
        }
        CP_COMMIT();
    };

    load_stage(0, 0);

    for (int i = 0; i < total; i++) {
        const int s = i & 1;
        if (i + 1 < total) { load_stage(s ^ 1, i + 1); CP_WAIT1(); }
        else               { CP_WAIT0(); }
        __syncthreads();

        const uint32_t sA = sbase + s * STAGE_BYTES;
        const uint32_t sB = sA + TILE_BYTES;
        uint32_t aAddr0 = sA + (uint32_t)((wm * 32 + a_row) * GPAD + a_kof) * 2;
        uint32_t aAddr1 = aAddr0 + (uint32_t)(16 * GPAD) * 2;
        uint32_t bAddr[4];
#pragma unroll
        for (int p = 0; p < 4; p++)
            bAddr[p] = sB + (uint32_t)((wn * 64 + p * 16 + b_nof) * GPAD + b_kof) * 2;

#pragma unroll
        for (int ks = 0; ks < 4; ks++) {
            const uint32_t ko = ks * 32;
            uint32_t a0[4], a1[4];
            ldsm_x4(a0[0], a0[1], a0[2], a0[3], aAddr0 + ko);
            ldsm_x4(a1[0], a1[1], a1[2], a1[3], aAddr1 + ko);
            uint32_t br[4][4];
#pragma unroll
            for (int p = 0; p < 4; p++)
                ldsm_x4(br[p][0], br[p][1], br[p][2], br[p][3], bAddr[p] + ko);
#pragma unroll
            for (int nt = 0; nt < 8; nt++) {
                const int p = nt >> 1, h = nt & 1;
                uint32_t b0 = br[p][h * 2], b1 = br[p][h * 2 + 1];
                mma16816(acc[0][nt][0], acc[0][nt][1], acc[0][nt][2], acc[0][nt][3],
                         a0[0], a0[1], a0[2], a0[3], b0, b1);
                mma16816(acc[1][nt][0], acc[1][nt][1], acc[1][nt][2], acc[1][nt][3],
                         a1[0], a1[1], a1[2], a1[3], b0, b1);
            }
        }
        __syncthreads();
    }

    const int crow = lane >> 2;
    const int ccol = (lane & 3) * 2;
#pragma unroll
    for (int mt = 0; mt < 2; mt++) {
        int m0 = bm + wm * 32 + mt * 16 + crow;
#pragma unroll
        for (int nt = 0; nt < 8; nt++) {
            int n0 = bn + wn * 64 + nt * 8 + ccol;
            *(float2*)(C + (size_t)m0 * N + n0)       = make_float2(acc[mt][nt][0], acc[mt][nt][1]);
            *(float2*)(C + (size_t)(m0 + 8) * N + n0) = make_float2(acc[mt][nt][2], acc[mt][nt][3]);
        }
    }
}

// ---------------- RMSNorm + RoPE + bf16 hi/lo split --------------------------
__global__ __launch_bounds__(256) void norm_rope_split(
    const float* __restrict__ X, const float* __restrict__ cosb,
    const float* __restrict__ sinb, const float* __restrict__ gamma,
    __nv_bfloat16* __restrict__ Xh, __nv_bfloat16* __restrict__ Xl,
    int nheads, int total_rows, float scale)
{
    int warp = (blockIdx.x * 256 + threadIdx.x) >> 5;
    int lane = threadIdx.x & 31;
    if (warp >= total_rows) return;
    int bs = warp / nheads;
    const float* x = X + (size_t)warp * DD;
    float v0 = x[lane];
    float v1 = x[lane + 32];
    float ss = v0 * v0 + v1 * v1;
#pragma unroll
    for (int o = 16; o > 0; o >>= 1) ss += __shfl_xor_sync(0xffffffffu, ss, o);
    float inv = rsqrtf(ss * (1.0f / DD) + EPS);
    float n0 = v0 * inv * gamma[lane];
    float n1 = v1 * inv * gamma[lane + 32];
    const float* cp = cosb + (size_t)bs * DD;
    const float* sp = sinb + (size_t)bs * DD;
    float r0 = (n0 * cp[lane]      - n1 * sp[lane])      * scale;
    float r1 = (n1 * cp[lane + 32] + n0 * sp[lane + 32]) * scale;
    __nv_bfloat16 h0 = __float2bfloat16(r0);
    __nv_bfloat16 h1 = __float2bfloat16(r1);
    Xh[(size_t)warp * DD + lane]      = h0;
    Xh[(size_t)warp * DD + lane + 32] = h1;
    Xl[(size_t)warp * DD + lane]      = __float2bfloat16(r0 - __bfloat162float(h0));
    Xl[(size_t)warp * DD + lane + 32] = __float2bfloat16(r1 - __bfloat162float(h1));
}

// ---------------- V: fp32 [b,s,kvh,d] -> bf16 hi/lo transposed [b,kvh,d,s] ---
__global__ __launch_bounds__(256) void split_v_trans(
    const float* __restrict__ V, __nv_bfloat16* __restrict__ Vth,
    __nv_bfloat16* __restrict__ Vtl)
{
    __shared__ float tile[64][65];
    const int sb = blockIdx.x * 64;
    const int kvh = blockIdx.y;
    const int b = blockIdx.z;
    const int tid = threadIdx.x;
#pragma unroll
    for (int i = tid; i < 1024; i += 256) {
        int r = i >> 4;
        int c4 = (i & 15) << 2;
        float4 v = *(const float4*)(V + ((size_t)(b * SS + sb + r) * NKV + kvh) * DD + c4);
        tile[r][c4 + 0] = v.x; tile[r][c4 + 1] = v.y;
        tile[r][c4 + 2] = v.z; tile[r][c4 + 3] = v.w;
    }
    __syncthreads();
#pragma unroll
    for (int i = tid; i < 1024; i += 256) {
        int d = i >> 4;
        int s4 = (i & 15) << 2;
        size_t base = ((size_t)(b * NKV + kvh) * DD + d) * SS + sb + s4;
        __nv_bfloat16 hs4[4], ls4[4];
#pragma unroll
        for (int j = 0; j < 4; j++) {
            float v = tile[s4 + j][d];
            hs4[j] = __float2bfloat16(v);
            ls4[j] = __float2bfloat16(v - __bfloat162float(hs4[j]));
        }
        *(__nv_bfloat162*)(Vth + base)     = __nv_bfloat162(hs4[0], hs4[1]);
        *(__nv_bfloat162*)(Vth + base + 2) = __nv_bfloat162(hs4[2], hs4[3]);
        *(__nv_bfloat162*)(Vtl + base)     = __nv_bfloat162(ls4[0], ls4[1]);
        *(__nv_bfloat162*)(Vtl + base + 2) = __nv_bfloat162(ls4[2], ls4[3]);
    }
}

// ---------------- HMMA flash attention, cp.async pipelined -------------------
// CTA: (qtile 128, head, batch). 8 warps x m16. KV tiles of 64, double-buffered.
// Stage: {Kh,Kl,Vh,Vl} 64x64 bf16 each, pitch 144B.
#define AT_PITCH 144
#define AT_TILE (64 * AT_PITCH)       // 9216
#define AT_STAGE (4 * AT_TILE)        // 36864
#define ATT_SMEM (2 * AT_STAGE)       // 73728

__global__ __launch_bounds__(256) void attn_hmma()
{
    extern __shared__ char sm8[];
    const uint32_t sbase = smem_u32(sm8);
    const int qt = blockIdx.x;
    const int h  = blockIdx.y;
    const int b  = blockIdx.z;
    const int kvh = h >> 3;
    const int tid = threadIdx.x;
    const int wid = tid >> 5;
    const int lane = tid & 31;
    const int g = lane >> 3, li = lane & 7;
    const int a_row = (g & 1) * 8 + li;
    const int a_kof = (g >> 1) * 8;
    const int b_nof = (g >> 1) * 8 + li;
    const int b_kof = (g & 1) * 8;
    const int lr = tid >> 3;     // 0..31
    const int lc = tid & 7;      // 16B chunk within 128B row

    // ---- group A: Q hi/lo into stage-1 area (Qh @ +AT_STAGE, Ql @ +AT_STAGE+18432)
    {
        const __nv_bfloat16* Qh = g_qh + ((size_t)(b * SS + qt * 128) * NH + h) * DD;
        const __nv_bfloat16* Ql = g_ql + ((size_t)(b * SS + qt * 128) * NH + h) * DD;
#pragma unroll
        for (int u = 0; u < 4; u++) {
            int r = u * 32 + lr;
            uint32_t dof = (uint32_t)r * AT_PITCH + lc * 16;
            CP_ASYNC16(sbase + AT_STAGE + dof,         Qh + (size_t)r * (NH * DD) + lc * 8);
            CP_ASYNC16(sbase + AT_STAGE + 18432 + dof, Ql + (size_t)r * (NH * DD) + lc * 8);
        }
        CP_COMMIT();
    }

    auto load_kv = [&](int s, int kt) {
        const __nv_bfloat16* Kh = g_kh + ((size_t)(b * SS + kt * 64) * NKV + kvh) * DD;
        const __nv_bfloat16* Kl = g_kl + ((size_t)(b * SS + kt * 64) * NKV + kvh) * DD;
        const __nv_bfloat16* Vh = g_vth + (size_t)(b * NKV + kvh) * DD * SS + kt * 64;
        const __nv_bfloat16* Vl = g_vtl + (size_t)(b * NKV + kvh) * DD * SS + kt * 64;
        const uint32_t sb0 = sbase + s * AT_STAGE;
#pragma unroll
        for (int u = 0; u < 8; u++) {
            const int t = u >> 1;
            const int r = (u & 1) * 32 + lr;
            uint32_t dst = sb0 + t * AT_TILE + (uint32_t)r * AT_PITCH + lc * 16;
            const __nv_bfloat16* src;
            if      (t == 0) src = Kh + (size_t)r * (NKV * DD) + lc * 8;
            else if (t == 1) src = Kl + (size_t)r * (NKV * DD) + lc * 8;
            else if (t == 2) src = Vh + (size_t)r * SS + lc * 8;
            else             src = Vl + (size_t)r * SS + lc * 8;
            CP_ASYNC16(dst, src);
        }
        CP_COMMIT();
    };

    // ---- group B: stage 0 (kt=0)
    load_kv(0, 0);

    // ---- wait for Q (group A), grab Q fragments
    CP_WAIT1();
    __syncthreads();
    uint32_t qfh[4][4], qfl[4][4];
#pragma unroll
    for (int ks = 0; ks < 4; ks++) {
        uint32_t off = (uint32_t)(wid * 16 + a_row) * AT_PITCH + (ks * 16 + a_kof) * 2;
        ldsm_x4(qfh[ks][0], qfh[ks][1], qfh[ks][2], qfh[ks][3], sbase + AT_STAGE + off);
        ldsm_x4(qfl[ks][0], qfl[ks][1], qfl[ks][2], qfl[ks][3], sbase + AT_STAGE + 18432 + off);
    }
    __syncthreads();   // all warps done reading stage-1 area before it is reused

    float O[8][4];
#pragma unroll
    for (int j = 0; j < 8; j++)
#pragma unroll
        for (int r = 0; r < 4; r++) O[j][r] = 0.f;
    float m0 = -1e30f, m1 = -1e30f, l0 = 0.f, l1 = 0.f;

    for (int kt = 0; kt < SS / 64; kt++) {
        const int s = kt & 1;
        if (kt + 1 < SS / 64) { load_kv(s ^ 1, kt + 1); CP_WAIT1(); }
        else                  { CP_WAIT0(); }
        __syncthreads();

        const uint32_t sKh = sbase + s * AT_STAGE;
        const uint32_t sKl = sKh + AT_TILE;
        const uint32_t sVh = sKh + 2 * AT_TILE;
        const uint32_t sVl = sKh + 3 * AT_TILE;

        // ---- S = QK^T (3 passes, fp32 accum)
        float sa[8][4];
#pragma unroll
        for (int j = 0; j < 8; j++)
#pragma unroll
            for (int r = 0; r < 4; r++) sa[j][r] = 0.f;
#pragma unroll
        for (int ks = 0; ks < 4; ks++) {
            const uint32_t ko = (uint32_t)(ks * 16 + b_kof) * 2;
            uint32_t kb4[4][4];
#pragma unroll
            for (int p = 0; p < 4; p++)
                ldsm_x4(kb4[p][0], kb4[p][1], kb4[p][2], kb4[p][3],
                        sKh + (uint32_t)(p * 16 + b_nof) * AT_PITCH + ko);
#pragma unroll
            for (int j = 0; j < 8; j++) {
                const int p = j >> 1, hh = j & 1;
                mma16816(sa[j][0], sa[j][1], sa[j][2], sa[j][3],
                         qfh[ks][0], qfh[ks][1], qfh[ks][2], qfh[ks][3],
                         kb4[p][hh * 2], kb4[p][hh * 2 + 1]);
                mma16816(sa[j][0], sa[j][1], sa[j][2], sa[j][3],
                         qfl[ks][0], qfl[ks][1], qfl[ks][2], qfl[ks][3],
                         kb4[p][hh * 2], kb4[p][hh * 2 + 1]);
            }
#pragma unroll
            for (int p = 0; p < 4; p++)
                ldsm_x4(kb4[p][0], kb4[p][1], kb4[p][2], kb4[p][3],
                        sKl + (uint32_t)(p * 16 + b_nof) * AT_PITCH + ko);
#pragma unroll
            for (int j = 0; j < 8; j++) {
                const int p = j >> 1, hh = j & 1;
                mma16816(sa[j][0], sa[j][1], sa[j][2], sa[j][3],
                         qfh[ks][0], qfh[ks][1], qfh[ks][2], qfh[ks][3],
                         kb4[p][hh * 2], kb4[p][hh * 2 + 1]);
            }
        }

        // ---- online softmax
        float tm0 = -1e30f, tm1 = -1e30f;
#pragma unroll
        for (int j = 0; j < 8; j++) {
            tm0 = fmaxf(tm0, fmaxf(sa[j][0], sa[j][1]));
            tm1 = fmaxf(tm1, fmaxf(sa[j][2], sa[j][3]));
        }
        tm0 = fmaxf(tm0, __shfl_xor_sync(0xffffffffu, tm0, 1));
        tm0 = fmaxf(tm0, __shfl_xor_sync(0xffffffffu, tm0, 2));
        tm1 = fmaxf(tm1, __shfl_xor_sync(0xffffffffu, tm1, 1));
        tm1 = fmaxf(tm1, __shfl_xor_sync(0xffffffffu, tm1, 2));
        float mn0 = fmaxf(m0, tm0), mn1 = fmaxf(m1, tm1);
        float al0 = __expf(m0 - mn0), al1 = __expf(m1 - mn1);
        m0 = mn0; m1 = mn1;
        float ls0 = 0.f, ls1 = 0.f;
#pragma unroll
        for (int j = 0; j < 8; j++) {
            sa[j][0] = __expf(sa[j][0] - m0);
            sa[j][1] = __expf(sa[j][1] - m0);
            sa[j][2] = __expf(sa[j][2] - m1);
            sa[j][3] = __expf(sa[j][3] - m1);
            ls0 += sa[j][0] + sa[j][1];
            ls1 += sa[j][2] + sa[j][3];
        }
        ls0 += __shfl_xor_sync(0xffffffffu, ls0, 1);
        ls0 += __shfl_xor_sync(0xffffffffu, ls0, 2);
        ls1 += __shfl_xor_sync(0xffffffffu, ls1, 1);
        ls1 += __shfl_xor_sync(0xffffffffu, ls1, 2);
        l0 = l0 * al0 + ls0;
        l1 = l1 * al1 + ls1;
#pragma unroll
        for (int j = 0; j < 8; j++) {
            O[j][0] *= al0; O[j][1] *= al0;
            O[j][2] *= al1; O[j][3] *= al1;
        }

        // ---- pack P hi/lo (C-frag -> A-frag layout)
        uint32_t pah[4][4], pal[4][4];
#pragma unroll
        for (int t = 0; t < 4; t++) {
            float e[8] = {sa[2*t][0], sa[2*t][1], sa[2*t][2], sa[2*t][3],
                          sa[2*t+1][0], sa[2*t+1][1], sa[2*t+1][2], sa[2*t+1][3]};
            float hi[8], lo[8];
#pragma unroll
            for (int u = 0; u < 8; u++) {
                hi[u] = __bfloat162float(__float2bfloat16(e[u]));
                lo[u] = e[u] - hi[u];
            }
            pah[t][0] = pack_bf162(hi[0], hi[1]);
            pah[t][1] = pack_bf162(hi[2], hi[3]);
            pah[t][2] = pack_bf162(hi[4], hi[5]);
            pah[t][3] = pack_bf162(hi[6], hi[7]);
            pal[t][0] = pack_bf162(lo[0], lo[1]);
            pal[t][1] = pack_bf162(lo[2], lo[3]);
            pal[t][2] = pack_bf162(lo[4], lo[5]);
            pal[t][3] = pack_bf162(lo[6], lo[7]);
        }

        // ---- O += Ph*Vh + Pl*Vh + Ph*Vl
#pragma unroll
        for (int t = 0; t < 4; t++) {
            const uint32_t ko = (uint32_t)(t * 16 + b_kof) * 2;
            uint32_t vb4[4][4];
#pragma unroll
            for (int p = 0; p < 4; p++)
                ldsm_x4(vb4[p][0], vb4[p][1], vb4[p][2], vb4[p][3],
                        sVh + (uint32_t)(p * 16 + b_nof) * AT_PITCH + ko);
#pragma unroll
            for (int j = 0; j < 8; j++) {
                const int p = j >> 1, hh = j & 1;
                mma16816(O[j][0], O[j][1], O[j][2], O[j][3],
                         pah[t][0], pah[t][1], pah[t][2], pah[t][3],
                         vb4[p][hh * 2], vb4[p][hh * 2 + 1]);
                mma16816(O[j][0], O[j][1], O[j][2], O[j][3],
                         pal[t][0], pal[t][1], pal[t][2], pal[t][3],
                         vb4[p][hh * 2], vb4[p][hh * 2 + 1]);
            }
#pragma unroll
            for (int p = 0; p < 4; p++)
                ldsm_x4(vb4[p][0], vb4[p][1], vb4[p][2], vb4[p][3],
                        sVl + (uint32_t)(p * 16 + b_nof) * AT_PITCH + ko);
#pragma unroll
            for (int j = 0; j < 8; j++) {
                const int p = j >> 1, hh = j & 1;
                mma16816(O[j][0], O[j][1], O[j][2], O[j][3],
                         pah[t][0], pah[t][1], pah[t][2], pah[t][3],
                         vb4[p][hh * 2], vb4[p][hh * 2 + 1]);
            }
        }
        __syncthreads();
    }

    // ---- epilogue: normalize, gate, store
    float inv0 = 1.f / l0, inv1 = 1.f / l1;
    int r0 = qt * 128 + wid * 16 + (lane >> 2);
    int r1 = r0 + 8;
    size_t base0 = ((size_t)(b * SS) + r0) * (NH * DD) + h * DD + ((lane & 3) << 1);
    size_t base1 = ((size_t)(b * SS) + r1) * (NH * DD) + h * DD + ((lane & 3) << 1);
#pragma unroll
    for (int j = 0; j < 8; j++) {
        float2 gA = *(const float2*)(d_gbuf + base0 + j * 8);
        float2 gB = *(const float2*)(d_gbuf + base1 + j * 8);
        float2 oA, oB;
        oA.x = O[j][0] * inv0 * (1.f / (1.f + __expf(-gA.x)));
        oA.y = O[j][1] * inv0 * (1.f / (1.f + __expf(-gA.y)));
        oB.x = O[j][2] * inv1 * (1.f / (1.f + __expf(-gB.x)));
        oB.y = O[j][3] * inv1 * (1.f / (1.f + __expf(-gB.y)));
        *(float2*)(d_abuf + base0 + j * 8) = oA;
        *(float2*)(d_abuf + base1 + j * 8) = oB;
    }
}

// ---------------- launch -----------------------------------------------------
extern "C" void kernel_launch(void* const* d_in, const int* in_sizes, int n_in,
                              void* d_out, int out_size)
{
    const float* hs   = (const float*)d_in[0];
    const float* cosb = (const float*)d_in[1];
    const float* sinb = (const float*)d_in[2];
    const float* Wq   = (const float*)d_in[3];
    const float* Wk   = (const float*)d_in[4];
    const float* Wv   = (const float*)d_in[5];
    const float* Wg   = (const float*)d_in[6];
    const float* Wo   = (const float*)d_in[7];
    const float* qg   = (const float*)d_in[8];
    const float* kg   = (const float*)d_in[9];
    float* out = (float*)d_out;

    float *qbuf, *kbuf, *vbuf, *gbuf, *abuf;
    cudaGetSymbolAddress((void**)&qbuf, d_qbuf);
    cudaGetSymbolAddress((void**)&kbuf, d_kbuf);
    cudaGetSymbolAddress((void**)&vbuf, d_vbuf);
    cudaGetSymbolAddress((void**)&gbuf, d_gbuf);
    cudaGetSymbolAddress((void**)&abuf, d_abuf);

    __nv_bfloat16 *hs_h, *hs_l, *wq_h, *wq_l, *wk_h, *wk_l, *wv_h, *wv_l;
    __nv_bfloat16 *wg_h, *wg_l, *wo_h, *wo_l, *ab_h, *ab_l;
    __nv_bfloat16 *qh, *ql, *kh, *kl, *vth, *vtl;
    cudaGetSymbolAddress((void**)&hs_h, g_hs_h);
    cudaGetSymbolAddress((void**)&hs_l, g_hs_l);
    cudaGetSymbolAddress((void**)&wq_h, g_wq_h);
    cudaGetSymbolAddress((void**)&wq_l, g_wq_l);
    cudaGetSymbolAddress((void**)&wk_h, g_wk_h);
    cudaGetSymbolAddress((void**)&wk_l, g_wk_l);
    cudaGetSymbolAddress((void**)&wv_h, g_wv_h);
    cudaGetSymbolAddress((void**)&wv_l, g_wv_l);
    cudaGetSymbolAddress((void**)&wg_h, g_wg_h);
    cudaGetSymbolAddress((void**)&wg_l, g_wg_l);
    cudaGetSymbolAddress((void**)&wo_h, g_wo_h);
    cudaGetSymbolAddress((void**)&wo_l, g_wo_l);
    cudaGetSymbolAddress((void**)&ab_h, g_ab_h);
    cudaGetSymbolAddress((void**)&ab_l, g_ab_l);
    cudaGetSymbolAddress((void**)&qh,  g_qh);
    cudaGetSymbolAddress((void**)&ql,  g_ql);
    cudaGetSymbolAddress((void**)&kh,  g_kh);
    cudaGetSymbolAddress((void**)&kl,  g_kl);
    cudaGetSymbolAddress((void**)&vth, g_vth);
    cudaGetSymbolAddress((void**)&vtl, g_vtl);

    cudaFuncSetAttribute(gemm_bf16x3, cudaFuncAttributeMaxDynamicSharedMemorySize, GEMM_SMEM);
    cudaFuncSetAttribute(attn_hmma, cudaFuncAttributeMaxDynamicSharedMemorySize, ATT_SMEM);

    // splits of inputs
    {
        int n4;
        n4 = MROWS * HID / 4;      split_bf16<<<(n4 + 255) / 256, 256>>>(hs, hs_h, hs_l, n4);
        n4 = NH * DD * HID / 4;    split_bf16<<<(n4 + 255) / 256, 256>>>(Wq, wq_h, wq_l, n4);
        n4 = NKV * DD * HID / 4;   split_bf16<<<(n4 + 255) / 256, 256>>>(Wk, wk_h, wk_l, n4);
        n4 = NKV * DD * HID / 4;   split_bf16<<<(n4 + 255) / 256, 256>>>(Wv, wv_h, wv_l, n4);
        n4 = NH * DD * HID / 4;    split_bf16<<<(n4 + 255) / 256, 256>>>(Wg, wg_h, wg_l, n4);
        n4 = HID * HID / 4;        split_bf16<<<(n4 + 255) / 256, 256>>>(Wo, wo_h, wo_l, n4);
    }

    // projections via HMMA
    gemm_bf16x3<<<dim3(NH * DD / 128, MROWS / 128), 256, GEMM_SMEM>>>(
        hs_h, hs_l, wq_h, wq_l, qbuf, MROWS, NH * DD, HID);
    gemm_bf16x3<<<dim3(NKV * DD / 128, MROWS / 128), 256, GEMM_SMEM>>>(
        hs_h, hs_l, wk_h, wk_l, kbuf, MROWS, NKV * DD, HID);
    gemm_bf16x3<<<dim3(NKV * DD / 128, MROWS / 128), 256, GEMM_SMEM>>>(
        hs_h, hs_l, wv_h, wv_l, vbuf, MROWS, NKV * DD, HID);
    gemm_bf16x3<<<dim3(NH * DD / 128, MROWS / 128), 256, GEMM_SMEM>>>(
        hs_h, hs_l, wg_h, wg_l, gbuf, MROWS, NH * DD, HID);

    // RMSNorm + RoPE + hi/lo split (Q scaled by D^-0.5), V transpose+split
    {
        int rows_q = MROWS * NH;
        int rows_k = MROWS * NKV;
        norm_rope_split<<<(rows_q * 32 + 255) / 256, 256>>>(
            qbuf, cosb, sinb, qg, qh, ql, NH, rows_q, QSCALE);
        norm_rope_split<<<(rows_k * 32 + 255) / 256, 256>>>(
            kbuf, cosb, sinb, kg, kh, kl, NKV, rows_k, 1.0f);
        split_v_trans<<<dim3(SS / 64, NKV, BB), 256>>>(vbuf, vth, vtl);
    }

    // attention (+ fused sigmoid gate) via HMMA, cp.async pipelined
    attn_hmma<<<dim3(SS / 128, NH, BB), 256, ATT_SMEM>>>();

    // split attention output, then output projection
    {
        int n4 = MROWS * HID / 4;
        split_bf16<<<(n4 + 255) / 256, 256>>>(abuf, ab_h, ab_l, n4);
    }
    gemm_bf16x3<<<dim3(HID / 128, MROWS / 128), 256, GEMM_SMEM>>>(
        ab_h, ab_l, wo_h, wo_l, out, MROWS, HID, HID);
}

// round 7
// speedup vs baseline: 2.9703x; 1.0836x over previous
#include <cuda_runtime.h>
#include <cuda_bf16.h>
#include <math.h>
#include <cstdint>

// Problem constants
#define BB 2
#define SS 2048
#define HID 2048
#define NH 32
#define NKV 4
#define DD 64
#define N_REP 8
#define MROWS (BB * SS)           // 4096
#define QSCALE 0.125f             // D^-0.5
#define EPS 1e-6f

// ---------------- async copy helpers ----------------------------------------
#define CP_ASYNC16(smem_u32a, gptr) \
    asm volatile("cp.async.cg.shared.global [%0], [%1], 16;" :: "r"(smem_u32a), "l"(gptr))
#define CP_COMMIT() asm volatile("cp.async.commit_group;" ::: "memory")
#define CP_WAIT1()  asm volatile("cp.async.wait_group 1;" ::: "memory")
#define CP_WAIT0()  asm volatile("cp.async.wait_group 0;" ::: "memory")

__device__ __forceinline__ uint32_t smem_u32(const void* p) {
    uint32_t a;
    asm("{ .reg .u64 t; cvta.to.shared.u64 t, %1; cvt.u32.u64 %0, t; }" : "=r"(a) : "l"(p));
    return a;
}
__device__ __forceinline__ void ldsm_x4(uint32_t& r0, uint32_t& r1, uint32_t& r2, uint32_t& r3,
                                        uint32_t addr) {
    asm volatile("ldmatrix.sync.aligned.m8n8.x4.shared.b16 {%0,%1,%2,%3}, [%4];"
                 : "=r"(r0), "=r"(r1), "=r"(r2), "=r"(r3) : "r"(addr));
}
__device__ __forceinline__ void mma16816(float& c0, float& c1, float& c2, float& c3,
                                         uint32_t a0, uint32_t a1, uint32_t a2, uint32_t a3,
                                         uint32_t b0, uint32_t b1) {
    asm volatile(
        "mma.sync.aligned.m16n8k16.row.col.f32.bf16.bf16.f32 "
        "{%0,%1,%2,%3}, {%4,%5,%6,%7}, {%8,%9}, {%0,%1,%2,%3};"
        : "+f"(c0), "+f"(c1), "+f"(c2), "+f"(c3)
        : "r"(a0), "r"(a1), "r"(a2), "r"(a3), "r"(b0), "r"(b1));
}
__device__ __forceinline__ uint32_t pack_bf162(float x, float y) {
    __nv_bfloat162 h = __floats2bfloat162_rn(x, y);
    return *reinterpret_cast<uint32_t*>(&h);
}

// ---------------- scratch (static device memory) ----------------------------
__device__ float d_qbuf[(size_t)MROWS * NH * DD];
__device__ float d_kbuf[(size_t)MROWS * NKV * DD];
__device__ float d_vbuf[(size_t)MROWS * NKV * DD];
__device__ float d_gbuf[(size_t)MROWS * NH * DD];

__device__ __nv_bfloat16 g_hs_h[(size_t)MROWS * HID];
__device__ __nv_bfloat16 g_hs_l[(size_t)MROWS * HID];
__device__ __nv_bfloat16 g_wq_h[(size_t)NH * DD * HID];
__device__ __nv_bfloat16 g_wq_l[(size_t)NH * DD * HID];
__device__ __nv_bfloat16 g_wk_h[(size_t)NKV * DD * HID];
__device__ __nv_bfloat16 g_wk_l[(size_t)NKV * DD * HID];
__device__ __nv_bfloat16 g_wv_h[(size_t)NKV * DD * HID];
__device__ __nv_bfloat16 g_wv_l[(size_t)NKV * DD * HID];
__device__ __nv_bfloat16 g_wg_h[(size_t)NH * DD * HID];
__device__ __nv_bfloat16 g_wg_l[(size_t)NH * DD * HID];
__device__ __nv_bfloat16 g_wo_h[(size_t)HID * HID];
__device__ __nv_bfloat16 g_wo_l[(size_t)HID * HID];
__device__ __nv_bfloat16 g_ab_h[(size_t)MROWS * HID];
__device__ __nv_bfloat16 g_ab_l[(size_t)MROWS * HID];

// pre-split attention operands (bf16 hi/lo)
__device__ __nv_bfloat16 g_qh[(size_t)MROWS * NH * DD];
__device__ __nv_bfloat16 g_ql[(size_t)MROWS * NH * DD];
__device__ __nv_bfloat16 g_kh[(size_t)MROWS * NKV * DD];
__device__ __nv_bfloat16 g_kl[(size_t)MROWS * NKV * DD];
__device__ __nv_bfloat16 g_vth[(size_t)MROWS * NKV * DD];  // [b][kvh][d][s]
__device__ __nv_bfloat16 g_vtl[(size_t)MROWS * NKV * DD];

// ---------------- split fp32 -> bf16 hi/lo ----------------------------------
__global__ __launch_bounds__(256) void split_bf16(
    const float* __restrict__ X, __nv_bfloat16* __restrict__ hi,
    __nv_bfloat16* __restrict__ lo, int n4)
{
    int i = blockIdx.x * 256 + threadIdx.x;
    if (i >= n4) return;
    float4 x = ((const float4*)X)[i];
    __nv_bfloat16 h0 = __float2bfloat16(x.x);
    __nv_bfloat16 h1 = __float2bfloat16(x.y);
    __nv_bfloat16 h2 = __float2bfloat16(x.z);
    __nv_bfloat16 h3 = __float2bfloat16(x.w);
    __nv_bfloat16 l0 = __float2bfloat16(x.x - __bfloat162float(h0));
    __nv_bfloat16 l1 = __float2bfloat16(x.y - __bfloat162float(h1));
    __nv_bfloat16 l2 = __float2bfloat16(x.z - __bfloat162float(h2));
    __nv_bfloat16 l3 = __float2bfloat16(x.w - __bfloat162float(h3));
    ((__nv_bfloat162*)hi)[2*i]     = __nv_bfloat162(h0, h1);
    ((__nv_bfloat162*)hi)[2*i + 1] = __nv_bfloat162(h2, h3);
    ((__nv_bfloat162*)lo)[2*i]     = __nv_bfloat162(l0, l1);
    ((__nv_bfloat162*)lo)[2*i + 1] = __nv_bfloat162(l2, l3);
}

// ---------------- HMMA bf16x3 GEMM: single K pass, 4 tiles/stage -------------
// C[m,n] = sum_k (AhBh + AhBl + AlBh). CTA 128x128, BK=64, 8 warps 32x64.
#define GPAD 72
#define G_TILE (128 * GPAD * 2)     // 18432 per tile
#define G_STAGE4 (4 * G_TILE)       // 73728 per stage
#define GEMM_SMEM (2 * G_STAGE4)    // 147456 double buffered

__global__ __launch_bounds__(256) void gemm_bf16x3(
    const __nv_bfloat16* __restrict__ Ah, const __nv_bfloat16* __restrict__ Al,
    const __nv_bfloat16* __restrict__ Bh, const __nv_bfloat16* __restrict__ Bl,
    float* __restrict__ C, int M, int N, int K)
{
    extern __shared__ char smem[];
    const uint32_t sbase = smem_u32(smem);
    const int tid = threadIdx.x;
    const int wid = tid >> 5;
    const int lane = tid & 31;
    const int wm = wid & 3;
    const int wn = wid >> 2;
    const int bm = blockIdx.y * 128;
    const int bn = blockIdx.x * 128;

    const int nchunk = K >> 6;
    const int lrow = tid >> 3;
    const int lcol = (tid & 7) * 8;

    const int g = lane >> 3, li = lane & 7;
    const int a_row = (g & 1) * 8 + li;
    const int a_kof = (g >> 1) * 8;
    const int b_nof = (g >> 1) * 8 + li;
    const int b_kof = (g & 1) * 8;

    float acc[2][8][4];
#pragma unroll
    for (int mt = 0; mt < 2; mt++)
#pragma unroll
        for (int nt = 0; nt < 8; nt++)
#pragma unroll
            for (int r = 0; r < 4; r++) acc[mt][nt][r] = 0.f;

    auto load_stage = [&](int s, int k0) {
        const uint32_t st = sbase + s * G_STAGE4;
#pragma unroll
        for (int u = 0; u < 4; u++) {
            int row = lrow + u * 32;
            uint32_t so = (uint32_t)(row * GPAD + lcol) * 2;
            const size_t ga = (size_t)(bm + row) * K + k0 + lcol;
            const size_t gb = (size_t)(bn + row) * K + k0 + lcol;
            CP_ASYNC16(st + so,              Ah + ga);
            CP_ASYNC16(st + G_TILE + so,     Al + ga);
            CP_ASYNC16(st + 2 * G_TILE + so, Bh + gb);
            CP_ASYNC16(st + 3 * G_TILE + so, Bl + gb);
        }
        CP_COMMIT();
    };

    load_stage(0, 0);

    for (int i = 0; i < nchunk; i++) {
        const int s = i & 1;
        if (i + 1 < nchunk) { load_stage(s ^ 1, (i + 1) << 6); CP_WAIT1(); }
        else                { CP_WAIT0(); }
        __syncthreads();

        const uint32_t st = sbase + s * G_STAGE4;
        const uint32_t aBase = st + (uint32_t)((wm * 32 + a_row) * GPAD + a_kof) * 2;
        const uint32_t bBase = st + 2 * G_TILE + (uint32_t)((wn * 64 + b_nof) * GPAD + b_kof) * 2;

#pragma unroll
        for (int ks = 0; ks < 4; ks++) {
            const uint32_t ko = ks * 32;
            uint32_t ah0[4], ah1[4], al0[4], al1[4];
            ldsm_x4(ah0[0], ah0[1], ah0[2], ah0[3], aBase + ko);
            ldsm_x4(ah1[0], ah1[1], ah1[2], ah1[3], aBase + (uint32_t)(16 * GPAD) * 2 + ko);
            ldsm_x4(al0[0], al0[1], al0[2], al0[3], aBase + G_TILE + ko);
            ldsm_x4(al1[0], al1[1], al1[2], al1[3], aBase + G_TILE + (uint32_t)(16 * GPAD) * 2 + ko);

            uint32_t bf[4][4];
#pragma unroll
            for (int p = 0; p < 4; p++)
                ldsm_x4(bf[p][0], bf[p][1], bf[p][2], bf[p][3],
                        bBase + (uint32_t)(p * 16 * GPAD) * 2 + ko);
#pragma unroll
            for (int nt = 0; nt < 8; nt++) {
                const int p = nt >> 1, h = nt & 1;
                uint32_t b0 = bf[p][h * 2], b1 = bf[p][h * 2 + 1];
                mma16816(acc[0][nt][0], acc[0][nt][1], acc[0][nt][2], acc[0][nt][3],
                         ah0[0], ah0[1], ah0[2], ah0[3], b0, b1);
                mma16816(acc[1][nt][0], acc[1][nt][1], acc[1][nt][2], acc[1][nt][3],
                         ah1[0], ah1[1], ah1[2], ah1[3], b0, b1);
                mma16816(acc[0][nt][0], acc[0][nt][1], acc[0][nt][2], acc[0][nt][3],
                         al0[0], al0[1], al0[2], al0[3], b0, b1);
                mma16816(acc[1][nt][0], acc[1][nt][1], acc[1][nt][2], acc[1][nt][3],
                         al1[0], al1[1], al1[2], al1[3], b0, b1);
            }
#pragma unroll
            for (int p = 0; p < 4; p++)
                ldsm_x4(bf[p][0], bf[p][1], bf[p][2], bf[p][3],
                        bBase + G_TILE + (uint32_t)(p * 16 * GPAD) * 2 + ko);
#pragma unroll
            for (int nt = 0; nt < 8; nt++) {
                const int p = nt >> 1, h = nt & 1;
                uint32_t b0 = bf[p][h * 2], b1 = bf[p][h * 2 + 1];
                mma16816(acc[0][nt][0], acc[0][nt][1], acc[0][nt][2], acc[0][nt][3],
                         ah0[0], ah0[1], ah0[2], ah0[3], b0, b1);
                mma16816(acc[1][nt][0], acc[1][nt][1], acc[1][nt][2], acc[1][nt][3],
                         ah1[0], ah1[1], ah1[2], ah1[3], b0, b1);
            }
        }
        __syncthreads();
    }

    const int crow = lane >> 2;
    const int ccol = (lane & 3) * 2;
#pragma unroll
    for (int mt = 0; mt < 2; mt++) {
        int m0 = bm + wm * 32 + mt * 16 + crow;
#pragma unroll
        for (int nt = 0; nt < 8; nt++) {
            int n0 = bn + wn * 64 + nt * 8 + ccol;
            *(float2*)(C + (size_t)m0 * N + n0)       = make_float2(acc[mt][nt][0], acc[mt][nt][1]);
            *(float2*)(C + (size_t)(m0 + 8) * N + n0) = make_float2(acc[mt][nt][2], acc[mt][nt][3]);
        }
    }
}

// ---------------- RMSNorm + RoPE + bf16 hi/lo split --------------------------
__global__ __launch_bounds__(256) void norm_rope_split(
    const float* __restrict__ X, const float* __restrict__ cosb,
    const float* __restrict__ sinb, const float* __restrict__ gamma,
    __nv_bfloat16* __restrict__ Xh, __nv_bfloat16* __restrict__ Xl,
    int nheads, int total_rows, float scale)
{
    int warp = (blockIdx.x * 256 + threadIdx.x) >> 5;
    int lane = threadIdx.x & 31;
    if (warp >= total_rows) return;
    int bs = warp / nheads;
    const float* x = X + (size_t)warp * DD;
    float v0 = x[lane];
    float v1 = x[lane + 32];
    float ss = v0 * v0 + v1 * v1;
#pragma unroll
    for (int o = 16; o > 0; o >>= 1) ss += __shfl_xor_sync(0xffffffffu, ss, o);
    float inv = rsqrtf(ss * (1.0f / DD) + EPS);
    float n0 = v0 * inv * gamma[lane];
    float n1 = v1 * inv * gamma[lane + 32];
    const float* cp = cosb + (size_t)bs * DD;
    const float* sp = sinb + (size_t)bs * DD;
    float r0 = (n0 * cp[lane]      - n1 * sp[lane])      * scale;
    float r1 = (n1 * cp[lane + 32] + n0 * sp[lane + 32]) * scale;
    __nv_bfloat16 h0 = __float2bfloat16(r0);
    __nv_bfloat16 h1 = __float2bfloat16(r1);
    Xh[(size_t)warp * DD + lane]      = h0;
    Xh[(size_t)warp * DD + lane + 32] = h1;
    Xl[(size_t)warp * DD + lane]      = __float2bfloat16(r0 - __bfloat162float(h0));
    Xl[(size_t)warp * DD + lane + 32] = __float2bfloat16(r1 - __bfloat162float(h1));
}

// ---------------- V: fp32 [b,s,kvh,d] -> bf16 hi/lo transposed [b,kvh,d,s] ---
__global__ __launch_bounds__(256) void split_v_trans(
    const float* __restrict__ V, __nv_bfloat16* __restrict__ Vth,
    __nv_bfloat16* __restrict__ Vtl)
{
    __shared__ float tile[64][65];
    const int sb = blockIdx.x * 64;
    const int kvh = blockIdx.y;
    const int b = blockIdx.z;
    const int tid = threadIdx.x;
#pragma unroll
    for (int i = tid; i < 1024; i += 256) {
        int r = i >> 4;
        int c4 = (i & 15) << 2;
        float4 v = *(const float4*)(V + ((size_t)(b * SS + sb + r) * NKV + kvh) * DD + c4);
        tile[r][c4 + 0] = v.x; tile[r][c4 + 1] = v.y;
        tile[r][c4 + 2] = v.z; tile[r][c4 + 3] = v.w;
    }
    __syncthreads();
#pragma unroll
    for (int i = tid; i < 1024; i += 256) {
        int d = i >> 4;
        int s4 = (i & 15) << 2;
        size_t base = ((size_t)(b * NKV + kvh) * DD + d) * SS + sb + s4;
        __nv_bfloat16 hs4[4], ls4[4];
#pragma unroll
        for (int j = 0; j < 4; j++) {
            float v = tile[s4 + j][d];
            hs4[j] = __float2bfloat16(v);
            ls4[j] = __float2bfloat16(v - __bfloat162float(hs4[j]));
        }
        *(__nv_bfloat162*)(Vth + base)     = __nv_bfloat162(hs4[0], hs4[1]);
        *(__nv_bfloat162*)(Vth + base + 2) = __nv_bfloat162(hs4[2], hs4[3]);
        *(__nv_bfloat162*)(Vtl + base)     = __nv_bfloat162(ls4[0], ls4[1]);
        *(__nv_bfloat162*)(Vtl + base + 2) = __nv_bfloat162(ls4[2], ls4[3]);
    }
}

// ---------------- HMMA flash attention, cp.async pipelined -------------------
#define AT_PITCH 144
#define AT_TILE (64 * AT_PITCH)       // 9216
#define AT_STAGE (4 * AT_TILE)        // 36864
#define ATT_SMEM (2 * AT_STAGE)       // 73728

__global__ __launch_bounds__(256) void attn_hmma()
{
    extern __shared__ char sm8[];
    const uint32_t sbase = smem_u32(sm8);
    const int qt = blockIdx.x;
    const int h  = blockIdx.y;
    const int b  = blockIdx.z;
    const int kvh = h >> 3;
    const int tid = threadIdx.x;
    const int wid = tid >> 5;
    const int lane = tid & 31;
    const int g = lane >> 3, li = lane & 7;
    const int a_row = (g & 1) * 8 + li;
    const int a_kof = (g >> 1) * 8;
    const int b_nof = (g >> 1) * 8 + li;
    const int b_kof = (g & 1) * 8;
    const int lr = tid >> 3;
    const int lc = tid & 7;

    // ---- group A: Q hi/lo into stage-1 area
    {
        const __nv_bfloat16* Qh = g_qh + ((size_t)(b * SS + qt * 128) * NH + h) * DD;
        const __nv_bfloat16* Ql = g_ql + ((size_t)(b * SS + qt * 128) * NH + h) * DD;
#pragma unroll
        for (int u = 0; u < 4; u++) {
            int r = u * 32 + lr;
            uint32_t dof = (uint32_t)r * AT_PITCH + lc * 16;
            CP_ASYNC16(sbase + AT_STAGE + dof,         Qh + (size_t)r * (NH * DD) + lc * 8);
            CP_ASYNC16(sbase + AT_STAGE + 18432 + dof, Ql + (size_t)r * (NH * DD) + lc * 8);
        }
        CP_COMMIT();
    }

    auto load_kv = [&](int s, int kt) {
        const __nv_bfloat16* Kh = g_kh + ((size_t)(b * SS + kt * 64) * NKV + kvh) * DD;
        const __nv_bfloat16* Kl = g_kl + ((size_t)(b * SS + kt * 64) * NKV + kvh) * DD;
        const __nv_bfloat16* Vh = g_vth + (size_t)(b * NKV + kvh) * DD * SS + kt * 64;
        const __nv_bfloat16* Vl = g_vtl + (size_t)(b * NKV + kvh) * DD * SS + kt * 64;
        const uint32_t sb0 = sbase + s * AT_STAGE;
#pragma unroll
        for (int u = 0; u < 8; u++) {
            const int t = u >> 1;
            const int r = (u & 1) * 32 + lr;
            uint32_t dst = sb0 + t * AT_TILE + (uint32_t)r * AT_PITCH + lc * 16;
            const __nv_bfloat16* src;
            if      (t == 0) src = Kh + (size_t)r * (NKV * DD) + lc * 8;
            else if (t == 1) src = Kl + (size_t)r * (NKV * DD) + lc * 8;
            else if (t == 2) src = Vh + (size_t)r * SS + lc * 8;
            else             src = Vl + (size_t)r * SS + lc * 8;
            CP_ASYNC16(dst, src);
        }
        CP_COMMIT();
    };

    load_kv(0, 0);

    CP_WAIT1();
    __syncthreads();
    uint32_t qfh[4][4], qfl[4][4];
#pragma unroll
    for (int ks = 0; ks < 4; ks++) {
        uint32_t off = (uint32_t)(wid * 16 + a_row) * AT_PITCH + (ks * 16 + a_kof) * 2;
        ldsm_x4(qfh[ks][0], qfh[ks][1], qfh[ks][2], qfh[ks][3], sbase + AT_STAGE + off);
        ldsm_x4(qfl[ks][0], qfl[ks][1], qfl[ks][2], qfl[ks][3], sbase + AT_STAGE + 18432 + off);
    }
    __syncthreads();

    float O[8][4];
#pragma unroll
    for (int j = 0; j < 8; j++)
#pragma unroll
        for (int r = 0; r < 4; r++) O[j][r] = 0.f;
    float m0 = -1e30f, m1 = -1e30f, l0 = 0.f, l1 = 0.f;

    for (int kt = 0; kt < SS / 64; kt++) {
        const int s = kt & 1;
        if (kt + 1 < SS / 64) { load_kv(s ^ 1, kt + 1); CP_WAIT1(); }
        else                  { CP_WAIT0(); }
        __syncthreads();

        const uint32_t sKh = sbase + s * AT_STAGE;
        const uint32_t sKl = sKh + AT_TILE;
        const uint32_t sVh = sKh + 2 * AT_TILE;
        const uint32_t sVl = sKh + 3 * AT_TILE;

        float sa[8][4];
#pragma unroll
        for (int j = 0; j < 8; j++)
#pragma unroll
            for (int r = 0; r < 4; r++) sa[j][r] = 0.f;
#pragma unroll
        for (int ks = 0; ks < 4; ks++) {
            const uint32_t ko = (uint32_t)(ks * 16 + b_kof) * 2;
            uint32_t kb4[4][4];
#pragma unroll
            for (int p = 0; p < 4; p++)
                ldsm_x4(kb4[p][0], kb4[p][1], kb4[p][2], kb4[p][3],
                        sKh + (uint32_t)(p * 16 + b_nof) * AT_PITCH + ko);
#pragma unroll
            for (int j = 0; j < 8; j++) {
                const int p = j >> 1, hh = j & 1;
                mma16816(sa[j][0], sa[j][1], sa[j][2], sa[j][3],
                         qfh[ks][0], qfh[ks][1], qfh[ks][2], qfh[ks][3],
                         kb4[p][hh * 2], kb4[p][hh * 2 + 1]);
                mma16816(sa[j][0], sa[j][1], sa[j][2], sa[j][3],
                         qfl[ks][0], qfl[ks][1], qfl[ks][2], qfl[ks][3],
                         kb4[p][hh * 2], kb4[p][hh * 2 + 1]);
            }
#pragma unroll
            for (int p = 0; p < 4; p++)
                ldsm_x4(kb4[p][0], kb4[p][1], kb4[p][2], kb4[p][3],
                        sKl + (uint32_t)(p * 16 + b_nof) * AT_PITCH + ko);
#pragma unroll
            for (int j = 0; j < 8; j++) {
                const int p = j >> 1, hh = j & 1;
                mma16816(sa[j][0], sa[j][1], sa[j][2], sa[j][3],
                         qfh[ks][0], qfh[ks][1], qfh[ks][2], qfh[ks][3],
                         kb4[p][hh * 2], kb4[p][hh * 2 + 1]);
            }
        }

        // ---- online softmax
        float tm0 = -1e30f, tm1 = -1e30f;
#pragma unroll
        for (int j = 0; j < 8; j++) {
            tm0 = fmaxf(tm0, fmaxf(sa[j][0], sa[j][1]));
            tm1 = fmaxf(tm1, fmaxf(sa[j][2], sa[j][3]));
        }
        tm0 = fmaxf(tm0, __shfl_xor_sync(0xffffffffu, tm0, 1));
        tm0 = fmaxf(tm0, __shfl_xor_sync(0xffffffffu, tm0, 2));
        tm1 = fmaxf(tm1, __shfl_xor_sync(0xffffffffu, tm1, 1));
        tm1 = fmaxf(tm1, __shfl_xor_sync(0xffffffffu, tm1, 2));
        float mn0 = fmaxf(m0, tm0), mn1 = fmaxf(m1, tm1);
        float al0 = __expf(m0 - mn0), al1 = __expf(m1 - mn1);
        m0 = mn0; m1 = mn1;
        float ls0 = 0.f, ls1 = 0.f;
#pragma unroll
        for (int j = 0; j < 8; j++) {
            sa[j][0] = __expf(sa[j][0] - m0);
            sa[j][1] = __expf(sa[j][1] - m0);
            sa[j][2] = __expf(sa[j][2] - m1);
            sa[j][3] = __expf(sa[j][3] - m1);
            ls0 += sa[j][0] + sa[j][1];
            ls1 += sa[j][2] + sa[j][3];
        }
        ls0 += __shfl_xor_sync(0xffffffffu, ls0, 1);
        ls0 += __shfl_xor_sync(0xffffffffu, ls0, 2);
        ls1 += __shfl_xor_sync(0xffffffffu, ls1, 1);
        ls1 += __shfl_xor_sync(0xffffffffu, ls1, 2);
        l0 = l0 * al0 + ls0;
        l1 = l1 * al1 + ls1;
#pragma unroll
        for (int j = 0; j < 8; j++) {
            O[j][0] *= al0; O[j][1] *= al0;
            O[j][2] *= al1; O[j][3] *= al1;
        }

        // ---- pack P hi/lo
        uint32_t pah[4][4], pal[4][4];
#pragma unroll
        for (int t = 0; t < 4; t++) {
            float e[8] = {sa[2*t][0], sa[2*t][1], sa[2*t][2], sa[2*t][3],
                          sa[2*t+1][0], sa[2*t+1][1], sa[2*t+1][2], sa[2*t+1][3]};
            float hi[8], lo[8];
#pragma unroll
            for (int u = 0; u < 8; u++) {
                hi[u] = __bfloat162float(__float2bfloat16(e[u]));
                lo[u] = e[u] - hi[u];
            }
            pah[t][0] = pack_bf162(hi[0], hi[1]);
            pah[t][1] = pack_bf162(hi[2], hi[3]);
            pah[t][2] = pack_bf162(hi[4], hi[5]);
            pah[t][3] = pack_bf162(hi[6], hi[7]);
            pal[t][0] = pack_bf162(lo[0], lo[1]);
            pal[t][1] = pack_bf162(lo[2], lo[3]);
            pal[t][2] = pack_bf162(lo[4], lo[5]);
            pal[t][3] = pack_bf162(lo[6], lo[7]);
        }

        // ---- O += Ph*Vh + Pl*Vh + Ph*Vl
#pragma unroll
        for (int t = 0; t < 4; t++) {
            const uint32_t ko = (uint32_t)(t * 16 + b_kof) * 2;
            uint32_t vb4[4][4];
#pragma unroll
            for (int p = 0; p < 4; p++)
                ldsm_x4(vb4[p][0], vb4[p][1], vb4[p][2], vb4[p][3],
                        sVh + (uint32_t)(p * 16 + b_nof) * AT_PITCH + ko);
#pragma unroll
            for (int j = 0; j < 8; j++) {
                const int p = j >> 1, hh = j & 1;
                mma16816(O[j][0], O[j][1], O[j][2], O[j][3],
                         pah[t][0], pah[t][1], pah[t][2], pah[t][3],
                         vb4[p][hh * 2], vb4[p][hh * 2 + 1]);
                mma16816(O[j][0], O[j][1], O[j][2], O[j][3],
                         pal[t][0], pal[t][1], pal[t][2], pal[t][3],
                         vb4[p][hh * 2], vb4[p][hh * 2 + 1]);
            }
#pragma unroll
            for (int p = 0; p < 4; p++)
                ldsm_x4(vb4[p][0], vb4[p][1], vb4[p][2], vb4[p][3],
                        sVl + (uint32_t)(p * 16 + b_nof) * AT_PITCH + ko);
#pragma unroll
            for (int j = 0; j < 8; j++) {
                const int p = j >> 1, hh = j & 1;
                mma16816(O[j][0], O[j][1], O[j][2], O[j][3],
                         pah[t][0], pah[t][1], pah[t][2], pah[t][3],
                         vb4[p][hh * 2], vb4[p][hh * 2 + 1]);
            }
        }
        __syncthreads();
    }

    // ---- epilogue: normalize, gate, write bf16 hi/lo directly
    float inv0 = 1.f / l0, inv1 = 1.f / l1;
    int r0 = qt * 128 + wid * 16 + (lane >> 2);
    int r1 = r0 + 8;
    size_t base0 = ((size_t)(b * SS) + r0) * (NH * DD) + h * DD + ((lane & 3) << 1);
    size_t base1 = ((size_t)(b * SS) + r1) * (NH * DD) + h * DD + ((lane & 3) << 1);
#pragma unroll
    for (int j = 0; j < 8; j++) {
        float2 gA = *(const float2*)(d_gbuf + base0 + j * 8);
        float2 gB = *(const float2*)(d_gbuf + base1 + j * 8);
        float vAx = O[j][0] * inv0 * (1.f / (1.f + __expf(-gA.x)));
        float vAy = O[j][1] * inv0 * (1.f / (1.f + __expf(-gA.y)));
        float vBx = O[j][2] * inv1 * (1.f / (1.f + __expf(-gB.x)));
        float vBy = O[j][3] * inv1 * (1.f / (1.f + __expf(-gB.y)));
        __nv_bfloat16 hAx = __float2bfloat16(vAx), hAy = __float2bfloat16(vAy);
        __nv_bfloat16 hBx = __float2bfloat16(vBx), hBy = __float2bfloat16(vBy);
        *(__nv_bfloat162*)(g_ab_h + base0 + j * 8) = __nv_bfloat162(hAx, hAy);
        *(__nv_bfloat162*)(g_ab_h + base1 + j * 8) = __nv_bfloat162(hBx, hBy);
        *(__nv_bfloat162*)(g_ab_l + base0 + j * 8) = __nv_bfloat162(
            __float2bfloat16(vAx - __bfloat162float(hAx)),
            __float2bfloat16(vAy - __bfloat162float(hAy)));
        *(__nv_bfloat162*)(g_ab_l + base1 + j * 8) = __nv_bfloat162(
            __float2bfloat16(vBx - __bfloat162float(hBx)),
            __float2bfloat16(vBy - __bfloat162float(hBy)));
    }
}

// ---------------- launch -----------------------------------------------------
extern "C" void kernel_launch(void* const* d_in, const int* in_sizes, int n_in,
                              void* d_out, int out_size)
{
    const float* hs   = (const float*)d_in[0];
    const float* cosb = (const float*)d_in[1];
    const float* sinb = (const float*)d_in[2];
    const float* Wq   = (const float*)d_in[3];
    const float* Wk   = (const float*)d_in[4];
    const float* Wv   = (const float*)d_in[5];
    const float* Wg   = (const float*)d_in[6];
    const float* Wo   = (const float*)d_in[7];
    const float* qg   = (const float*)d_in[8];
    const float* kg   = (const float*)d_in[9];
    float* out = (float*)d_out;

    float *qbuf, *kbuf, *vbuf, *gbuf;
    cudaGetSymbolAddress((void**)&qbuf, d_qbuf);
    cudaGetSymbolAddress((void**)&kbuf, d_kbuf);
    cudaGetSymbolAddress((void**)&vbuf, d_vbuf);
    cudaGetSymbolAddress((void**)&gbuf, d_gbuf);

    __nv_bfloat16 *hs_h, *hs_l, *wq_h, *wq_l, *wk_h, *wk_l, *wv_h, *wv_l;
    __nv_bfloat16 *wg_h, *wg_l, *wo_h, *wo_l, *ab_h, *ab_l;
    __nv_bfloat16 *qh, *ql, *kh, *kl, *vth, *vtl;
    cudaGetSymbolAddress((void**)&hs_h, g_hs_h);
    cudaGetSymbolAddress((void**)&hs_l, g_hs_l);
    cudaGetSymbolAddress((void**)&wq_h, g_wq_h);
    cudaGetSymbolAddress((void**)&wq_l, g_wq_l);
    cudaGetSymbolAddress((void**)&wk_h, g_wk_h);
    cudaGetSymbolAddress((void**)&wk_l, g_wk_l);
    cudaGetSymbolAddress((void**)&wv_h, g_wv_h);
    cudaGetSymbolAddress((void**)&wv_l, g_wv_l);
    cudaGetSymbolAddress((void**)&wg_h, g_wg_h);
    cudaGetSymbolAddress((void**)&wg_l, g_wg_l);
    cudaGetSymbolAddress((void**)&wo_h, g_wo_h);
    cudaGetSymbolAddress((void**)&wo_l, g_wo_l);
    cudaGetSymbolAddress((void**)&ab_h, g_ab_h);
    cudaGetSymbolAddress((void**)&ab_l, g_ab_l);
    cudaGetSymbolAddress((void**)&qh,  g_qh);
    cudaGetSymbolAddress((void**)&ql,  g_ql);
    cudaGetSymbolAddress((void**)&kh,  g_kh);
    cudaGetSymbolAddress((void**)&kl,  g_kl);
    cudaGetSymbolAddress((void**)&vth, g_vth);
    cudaGetSymbolAddress((void**)&vtl, g_vtl);

    cudaFuncSetAttribute(gemm_bf16x3, cudaFuncAttributeMaxDynamicSharedMemorySize, GEMM_SMEM);
    cudaFuncSetAttribute(attn_hmma, cudaFuncAttributeMaxDynamicSharedMemorySize, ATT_SMEM);

    // splits of inputs
    {
        int n4;
        n4 = MROWS * HID / 4;      split_bf16<<<(n4 + 255) / 256, 256>>>(hs, hs_h, hs_l, n4);
        n4 = NH * DD * HID / 4;    split_bf16<<<(n4 + 255) / 256, 256>>>(Wq, wq_h, wq_l, n4);
        n4 = NKV * DD * HID / 4;   split_bf16<<<(n4 + 255) / 256, 256>>>(Wk, wk_h, wk_l, n4);
        n4 = NKV * DD * HID / 4;   split_bf16<<<(n4 + 255) / 256, 256>>>(Wv, wv_h, wv_l, n4);
        n4 = NH * DD * HID / 4;    split_bf16<<<(n4 + 255) / 256, 256>>>(Wg, wg_h, wg_l, n4);
        n4 = HID * HID / 4;        split_bf16<<<(n4 + 255) / 256, 256>>>(Wo, wo_h, wo_l, n4);
    }

    // projections via HMMA
    gemm_bf16x3<<<dim3(NH * DD / 128, MROWS / 128), 256, GEMM_SMEM>>>(
        hs_h, hs_l, wq_h, wq_l, qbuf, MROWS, NH * DD, HID);
    gemm_bf16x3<<<dim3(NKV * DD / 128, MROWS / 128), 256, GEMM_SMEM>>>(
        hs_h, hs_l, wk_h, wk_l, kbuf, MROWS, NKV * DD, HID);
    gemm_bf16x3<<<dim3(NKV * DD / 128, MROWS / 128), 256, GEMM_SMEM>>>(
        hs_h, hs_l, wv_h, wv_l, vbuf, MROWS, NKV * DD, HID);
    gemm_bf16x3<<<dim3(NH * DD / 128, MROWS / 128), 256, GEMM_SMEM>>>(
        hs_h, hs_l, wg_h, wg_l, gbuf, MROWS, NH * DD, HID);

    // RMSNorm + RoPE + hi/lo split (Q scaled), V transpose+split
    {
        int rows_q = MROWS * NH;
        int rows_k = MROWS * NKV;
        norm_rope_split<<<(rows_q * 32 + 255) / 256, 256>>>(
            qbuf, cosb, sinb, qg, qh, ql, NH, rows_q, QSCALE);
        norm_rope_split<<<(rows_k * 32 + 255) / 256, 256>>>(
            kbuf, cosb, sinb, kg, kh, kl, NKV, rows_k, 1.0f);
        split_v_trans<<<dim3(SS / 64, NKV, BB), 256>>>(vbuf, vth, vtl);
    }

    // attention (+ fused sigmoid gate, writes ab hi/lo directly)
    attn_hmma<<<dim3(SS / 128, NH, BB), 256, ATT_SMEM>>>();

    // output projection
    gemm_bf16x3<<<dim3(HID / 128, MROWS / 128), 256, GEMM_SMEM>>>(
        ab_h, ab_l, wo_h, wo_l, out, MROWS, HID, HID);
}

// round 8
// speedup vs baseline: 3.3187x; 1.1173x over previous
#include <cuda_runtime.h>
#include <cuda_bf16.h>
#include <math.h>
#include <cstdint>

// Problem constants
#define BB 2
#define SS 2048
#define HID 2048
#define NH 32
#define NKV 4
#define DD 64
#define N_REP 8
#define MROWS (BB * SS)           // 4096
#define QSCALE 0.125f             // D^-0.5
#define EPS 1e-6f

// fused projection layout: [Wq(2048) ; Wk(256) ; Wv(256) ; Wg(2048)]
#define NQKVG 4608
#define COL_Q 0
#define COL_K 2048
#define COL_V 2304
#define COL_G 2560

// ---------------- async copy helpers ----------------------------------------
#define CP_ASYNC16(smem_u32a, gptr) \
    asm volatile("cp.async.cg.shared.global [%0], [%1], 16;" :: "r"(smem_u32a), "l"(gptr))
#define CP_COMMIT() asm volatile("cp.async.commit_group;" ::: "memory")
#define CP_WAIT2()  asm volatile("cp.async.wait_group 2;" ::: "memory")
#define CP_WAIT1()  asm volatile("cp.async.wait_group 1;" ::: "memory")
#define CP_WAIT0()  asm volatile("cp.async.wait_group 0;" ::: "memory")

__device__ __forceinline__ uint32_t smem_u32(const void* p) {
    uint32_t a;
    asm("{ .reg .u64 t; cvta.to.shared.u64 t, %1; cvt.u32.u64 %0, t; }" : "=r"(a) : "l"(p));
    return a;
}
__device__ __forceinline__ void ldsm_x4(uint32_t& r0, uint32_t& r1, uint32_t& r2, uint32_t& r3,
                                        uint32_t addr) {
    asm volatile("ldmatrix.sync.aligned.m8n8.x4.shared.b16 {%0,%1,%2,%3}, [%4];"
                 : "=r"(r0), "=r"(r1), "=r"(r2), "=r"(r3) : "r"(addr));
}
__device__ __forceinline__ void mma16816(float& c0, float& c1, float& c2, float& c3,
                                         uint32_t a0, uint32_t a1, uint32_t a2, uint32_t a3,
                                         uint32_t b0, uint32_t b1) {
    asm volatile(
        "mma.sync.aligned.m16n8k16.row.col.f32.bf16.bf16.f32 "
        "{%0,%1,%2,%3}, {%4,%5,%6,%7}, {%8,%9}, {%0,%1,%2,%3};"
        : "+f"(c0), "+f"(c1), "+f"(c2), "+f"(c3)
        : "r"(a0), "r"(a1), "r"(a2), "r"(a3), "r"(b0), "r"(b1));
}
__device__ __forceinline__ uint32_t pack_bf162(float x, float y) {
    __nv_bfloat162 h = __floats2bfloat162_rn(x, y);
    return *reinterpret_cast<uint32_t*>(&h);
}

// ---------------- scratch (static device memory) ----------------------------
__device__ float d_qkvg[(size_t)MROWS * NQKVG];   // fused projection output

__device__ __nv_bfloat16 g_hs_h[(size_t)MROWS * HID];
__device__ __nv_bfloat16 g_hs_l[(size_t)MROWS * HID];
__device__ __nv_bfloat16 g_wqkvg_h[(size_t)NQKVG * HID];
__device__ __nv_bfloat16 g_wqkvg_l[(size_t)NQKVG * HID];
__device__ __nv_bfloat16 g_wo_h[(size_t)HID * HID];
__device__ __nv_bfloat16 g_wo_l[(size_t)HID * HID];
__device__ __nv_bfloat16 g_ab_h[(size_t)MROWS * HID];
__device__ __nv_bfloat16 g_ab_l[(size_t)MROWS * HID];

// pre-split attention operands (bf16 hi/lo)
__device__ __nv_bfloat16 g_qh[(size_t)MROWS * NH * DD];
__device__ __nv_bfloat16 g_ql[(size_t)MROWS * NH * DD];
__device__ __nv_bfloat16 g_kh[(size_t)MROWS * NKV * DD];
__device__ __nv_bfloat16 g_kl[(size_t)MROWS * NKV * DD];
__device__ __nv_bfloat16 g_vth[(size_t)MROWS * NKV * DD];  // [b][kvh][d][s]
__device__ __nv_bfloat16 g_vtl[(size_t)MROWS * NKV * DD];

// ---------------- split fp32 -> bf16 hi/lo ----------------------------------
__global__ __launch_bounds__(256) void split_bf16(
    const float* __restrict__ X, __nv_bfloat16* __restrict__ hi,
    __nv_bfloat16* __restrict__ lo, int n4)
{
    int i = blockIdx.x * 256 + threadIdx.x;
    if (i >= n4) return;
    float4 x = ((const float4*)X)[i];
    __nv_bfloat16 h0 = __float2bfloat16(x.x);
    __nv_bfloat16 h1 = __float2bfloat16(x.y);
    __nv_bfloat16 h2 = __float2bfloat16(x.z);
    __nv_bfloat16 h3 = __float2bfloat16(x.w);
    __nv_bfloat16 l0 = __float2bfloat16(x.x - __bfloat162float(h0));
    __nv_bfloat16 l1 = __float2bfloat16(x.y - __bfloat162float(h1));
    __nv_bfloat16 l2 = __float2bfloat16(x.z - __bfloat162float(h2));
    __nv_bfloat16 l3 = __float2bfloat16(x.w - __bfloat162float(h3));
    ((__nv_bfloat162*)hi)[2*i]     = __nv_bfloat162(h0, h1);
    ((__nv_bfloat162*)hi)[2*i + 1] = __nv_bfloat162(h2, h3);
    ((__nv_bfloat162*)lo)[2*i]     = __nv_bfloat162(l0, l1);
    ((__nv_bfloat162*)lo)[2*i + 1] = __nv_bfloat162(l2, l3);
}

// ---------------- HMMA bf16x3 GEMM: single K pass, 3-stage pipeline ----------
// C[m,n] = sum_k (AhBh + AhBl + AlBh). CTA 128x128, BK=64, 8 warps 32x64.
#define GPAD 72
#define G_TILE (128 * GPAD * 2)     // 18432 per tile
#define G_STAGE4 (4 * G_TILE)       // 73728 per stage
#define GEMM_SMEM (3 * G_STAGE4)    // 221184, 3-stage

__global__ __launch_bounds__(256) void gemm_bf16x3(
    const __nv_bfloat16* __restrict__ Ah, const __nv_bfloat16* __restrict__ Al,
    const __nv_bfloat16* __restrict__ Bh, const __nv_bfloat16* __restrict__ Bl,
    float* __restrict__ C, int M, int N, int K)
{
    extern __shared__ char smem[];
    const uint32_t sbase = smem_u32(smem);
    const int tid = threadIdx.x;
    const int wid = tid >> 5;
    const int lane = tid & 31;
    const int wm = wid & 3;
    const int wn = wid >> 2;
    const int bm = blockIdx.y * 128;
    const int bn = blockIdx.x * 128;

    const int nchunk = K >> 6;
    const int lrow = tid >> 3;
    const int lcol = (tid & 7) * 8;

    const int g = lane >> 3, li = lane & 7;
    const int a_row = (g & 1) * 8 + li;
    const int a_kof = (g >> 1) * 8;
    const int b_nof = (g >> 1) * 8 + li;
    const int b_kof = (g & 1) * 8;

    float acc[2][8][4];
#pragma unroll
    for (int mt = 0; mt < 2; mt++)
#pragma unroll
        for (int nt = 0; nt < 8; nt++)
#pragma unroll
            for (int r = 0; r < 4; r++) acc[mt][nt][r] = 0.f;

    auto load_stage = [&](int s, int k0) {
        const uint32_t st = sbase + s * G_STAGE4;
#pragma unroll
        for (int u = 0; u < 4; u++) {
            int row = lrow + u * 32;
            uint32_t so = (uint32_t)(row * GPAD + lcol) * 2;
            const size_t ga = (size_t)(bm + row) * K + k0 + lcol;
            const size_t gb = (size_t)(bn + row) * K + k0 + lcol;
            CP_ASYNC16(st + so,              Ah + ga);
            CP_ASYNC16(st + G_TILE + so,     Al + ga);
            CP_ASYNC16(st + 2 * G_TILE + so, Bh + gb);
            CP_ASYNC16(st + 3 * G_TILE + so, Bl + gb);
        }
        CP_COMMIT();
    };

    load_stage(0, 0);
    if (nchunk > 1) load_stage(1, 64);

    for (int i = 0; i < nchunk; i++) {
        const int s = i % 3;
        if (i + 2 < nchunk)      { load_stage((i + 2) % 3, (i + 2) << 6); CP_WAIT2(); }
        else if (i + 1 < nchunk) { CP_WAIT1(); }
        else                     { CP_WAIT0(); }
        __syncthreads();

        const uint32_t st = sbase + s * G_STAGE4;
        const uint32_t aBase = st + (uint32_t)((wm * 32 + a_row) * GPAD + a_kof) * 2;
        const uint32_t bBase = st + 2 * G_TILE + (uint32_t)((wn * 64 + b_nof) * GPAD + b_kof) * 2;

#pragma unroll
        for (int ks = 0; ks < 4; ks++) {
            const uint32_t ko = ks * 32;
            uint32_t ah0[4], ah1[4], al0[4], al1[4];
            ldsm_x4(ah0[0], ah0[1], ah0[2], ah0[3], aBase + ko);
            ldsm_x4(ah1[0], ah1[1], ah1[2], ah1[3], aBase + (uint32_t)(16 * GPAD) * 2 + ko);
            ldsm_x4(al0[0], al0[1], al0[2], al0[3], aBase + G_TILE + ko);
            ldsm_x4(al1[0], al1[1], al1[2], al1[3], aBase + G_TILE + (uint32_t)(16 * GPAD) * 2 + ko);

            uint32_t bf[4][4];
#pragma unroll
            for (int p = 0; p < 4; p++)
                ldsm_x4(bf[p][0], bf[p][1], bf[p][2], bf[p][3],
                        bBase + (uint32_t)(p * 16 * GPAD) * 2 + ko);
#pragma unroll
            for (int nt = 0; nt < 8; nt++) {
                const int p = nt >> 1, h = nt & 1;
                uint32_t b0 = bf[p][h * 2], b1 = bf[p][h * 2 + 1];
                mma16816(acc[0][nt][0], acc[0][nt][1], acc[0][nt][2], acc[0][nt][3],
                         ah0[0], ah0[1], ah0[2], ah0[3], b0, b1);
                mma16816(acc[1][nt][0], acc[1][nt][1], acc[1][nt][2], acc[1][nt][3],
                         ah1[0], ah1[1], ah1[2], ah1[3], b0, b1);
                mma16816(acc[0][nt][0], acc[0][nt][1], acc[0][nt][2], acc[0][nt][3],
                         al0[0], al0[1], al0[2], al0[3], b0, b1);
                mma16816(acc[1][nt][0], acc[1][nt][1], acc[1][nt][2], acc[1][nt][3],
                         al1[0], al1[1], al1[2], al1[3], b0, b1);
            }
#pragma unroll
            for (int p = 0; p < 4; p++)
                ldsm_x4(bf[p][0], bf[p][1], bf[p][2], bf[p][3],
                        bBase + G_TILE + (uint32_t)(p * 16 * GPAD) * 2 + ko);
#pragma unroll
            for (int nt = 0; nt < 8; nt++) {
                const int p = nt >> 1, h = nt & 1;
                uint32_t b0 = bf[p][h * 2], b1 = bf[p][h * 2 + 1];
                mma16816(acc[0][nt][0], acc[0][nt][1], acc[0][nt][2], acc[0][nt][3],
                         ah0[0], ah0[1], ah0[2], ah0[3], b0, b1);
                mma16816(acc[1][nt][0], acc[1][nt][1], acc[1][nt][2], acc[1][nt][3],
                         ah1[0], ah1[1], ah1[2], ah1[3], b0, b1);
            }
        }
        __syncthreads();
    }

    const int crow = lane >> 2;
    const int ccol = (lane & 3) * 2;
#pragma unroll
    for (int mt = 0; mt < 2; mt++) {
        int m0 = bm + wm * 32 + mt * 16 + crow;
#pragma unroll
        for (int nt = 0; nt < 8; nt++) {
            int n0 = bn + wn * 64 + nt * 8 + ccol;
            *(float2*)(C + (size_t)m0 * N + n0)       = make_float2(acc[mt][nt][0], acc[mt][nt][1]);
            *(float2*)(C + (size_t)(m0 + 8) * N + n0) = make_float2(acc[mt][nt][2], acc[mt][nt][3]);
        }
    }
}

// ---------------- RMSNorm + RoPE + bf16 hi/lo split (strided input) ----------
__global__ __launch_bounds__(256) void norm_rope_split(
    const float* __restrict__ X, const float* __restrict__ cosb,
    const float* __restrict__ sinb, const float* __restrict__ gamma,
    __nv_bfloat16* __restrict__ Xh, __nv_bfloat16* __restrict__ Xl,
    int nheads, int total_rows, float scale, int rowstride, int colbase)
{
    int warp = (blockIdx.x * 256 + threadIdx.x) >> 5;
    int lane = threadIdx.x & 31;
    if (warp >= total_rows) return;
    int bs = warp / nheads;
    int h  = warp - bs * nheads;
    const float* x = X + (size_t)bs * rowstride + colbase + h * DD;
    float v0 = x[lane];
    float v1 = x[lane + 32];
    float ss = v0 * v0 + v1 * v1;
#pragma unroll
    for (int o = 16; o > 0; o >>= 1) ss += __shfl_xor_sync(0xffffffffu, ss, o);
    float inv = rsqrtf(ss * (1.0f / DD) + EPS);
    float n0 = v0 * inv * gamma[lane];
    float n1 = v1 * inv * gamma[lane + 32];
    const float* cp = cosb + (size_t)bs * DD;
    const float* sp = sinb + (size_t)bs * DD;
    float r0 = (n0 * cp[lane]      - n1 * sp[lane])      * scale;
    float r1 = (n1 * cp[lane + 32] + n0 * sp[lane + 32]) * scale;
    __nv_bfloat16 h0 = __float2bfloat16(r0);
    __nv_bfloat16 h1 = __float2bfloat16(r1);
    Xh[(size_t)warp * DD + lane]      = h0;
    Xh[(size_t)warp * DD + lane + 32] = h1;
    Xl[(size_t)warp * DD + lane]      = __float2bfloat16(r0 - __bfloat162float(h0));
    Xl[(size_t)warp * DD + lane + 32] = __float2bfloat16(r1 - __bfloat162float(h1));
}

// ---------------- V: fp32 strided -> bf16 hi/lo transposed [b,kvh,d,s] -------
__global__ __launch_bounds__(256) void split_v_trans(
    const float* __restrict__ QKVG, __nv_bfloat16* __restrict__ Vth,
    __nv_bfloat16* __restrict__ Vtl)
{
    __shared__ float tile[64][65];
    const int sb = blockIdx.x * 64;
    const int kvh = blockIdx.y;
    const int b = blockIdx.z;
    const int tid = threadIdx.x;
#pragma unroll
    for (int i = tid; i < 1024; i += 256) {
        int r = i >> 4;
        int c4 = (i & 15) << 2;
        float4 v = *(const float4*)(QKVG + (size_t)(b * SS + sb + r) * NQKVG + COL_V + kvh * DD + c4);
        tile[r][c4 + 0] = v.x; tile[r][c4 + 1] = v.y;
        tile[r][c4 + 2] = v.z; tile[r][c4 + 3] = v.w;
    }
    __syncthreads();
#pragma unroll
    for (int i = tid; i < 1024; i += 256) {
        int d = i >> 4;
        int s4 = (i & 15) << 2;
        size_t base = ((size_t)(b * NKV + kvh) * DD + d) * SS + sb + s4;
        __nv_bfloat16 hs4[4], ls4[4];
#pragma unroll
        for (int j = 0; j < 4; j++) {
            float v = tile[s4 + j][d];
            hs4[j] = __float2bfloat16(v);
            ls4[j] = __float2bfloat16(v - __bfloat162float(hs4[j]));
        }
        *(__nv_bfloat162*)(Vth + base)     = __nv_bfloat162(hs4[0], hs4[1]);
        *(__nv_bfloat162*)(Vth + base + 2) = __nv_bfloat162(hs4[2], hs4[3]);
        *(__nv_bfloat162*)(Vtl + base)     = __nv_bfloat162(ls4[0], ls4[1]);
        *(__nv_bfloat162*)(Vtl + base + 2) = __nv_bfloat162(ls4[2], ls4[3]);
    }
}

// ---------------- HMMA flash attention, cp.async pipelined -------------------
#define AT_PITCH 144
#define AT_TILE (64 * AT_PITCH)       // 9216
#define AT_STAGE (4 * AT_TILE)        // 36864
#define ATT_SMEM (2 * AT_STAGE)       // 73728

__global__ __launch_bounds__(256) void attn_hmma()
{
    extern __shared__ char sm8[];
    const uint32_t sbase = smem_u32(sm8);
    const int qt = blockIdx.x;
    const int h  = blockIdx.y;
    const int b  = blockIdx.z;
    const int kvh = h >> 3;
    const int tid = threadIdx.x;
    const int wid = tid >> 5;
    const int lane = tid & 31;
    const int g = lane >> 3, li = lane & 7;
    const int a_row = (g & 1) * 8 + li;
    const int a_kof = (g >> 1) * 8;
    const int b_nof = (g >> 1) * 8 + li;
    const int b_kof = (g & 1) * 8;
    const int lr = tid >> 3;
    const int lc = tid & 7;

    // ---- group A: Q hi/lo into stage-1 area
    {
        const __nv_bfloat16* Qh = g_qh + ((size_t)(b * SS + qt * 128) * NH + h) * DD;
        const __nv_bfloat16* Ql = g_ql + ((size_t)(b * SS + qt * 128) * NH + h) * DD;
#pragma unroll
        for (int u = 0; u < 4; u++) {
            int r = u * 32 + lr;
            uint32_t dof = (uint32_t)r * AT_PITCH + lc * 16;
            CP_ASYNC16(sbase + AT_STAGE + dof,         Qh + (size_t)r * (NH * DD) + lc * 8);
            CP_ASYNC16(sbase + AT_STAGE + 18432 + dof, Ql + (size_t)r * (NH * DD) + lc * 8);
        }
        CP_COMMIT();
    }

    auto load_kv = [&](int s, int kt) {
        const __nv_bfloat16* Kh = g_kh + ((size_t)(b * SS + kt * 64) * NKV + kvh) * DD;
        const __nv_bfloat16* Kl = g_kl + ((size_t)(b * SS + kt * 64) * NKV + kvh) * DD;
        const __nv_bfloat16* Vh = g_vth + (size_t)(b * NKV + kvh) * DD * SS + kt * 64;
        const __nv_bfloat16* Vl = g_vtl + (size_t)(b * NKV + kvh) * DD * SS + kt * 64;
        const uint32_t sb0 = sbase + s * AT_STAGE;
#pragma unroll
        for (int u = 0; u < 8; u++) {
            const int t = u >> 1;
            const int r = (u & 1) * 32 + lr;
            uint32_t dst = sb0 + t * AT_TILE + (uint32_t)r * AT_PITCH + lc * 16;
            const __nv_bfloat16* src;
            if      (t == 0) src = Kh + (size_t)r * (NKV * DD) + lc * 8;
            else if (t == 1) src = Kl + (size_t)r * (NKV * DD) + lc * 8;
            else if (t == 2) src = Vh + (size_t)r * SS + lc * 8;
            else             src = Vl + (size_t)r * SS + lc * 8;
            CP_ASYNC16(dst, src);
        }
        CP_COMMIT();
    };

    load_kv(0, 0);

    CP_WAIT1();
    __syncthreads();
    uint32_t qfh[4][4], qfl[4][4];
#pragma unroll
    for (int ks = 0; ks < 4; ks++) {
        uint32_t off = (uint32_t)(wid * 16 + a_row) * AT_PITCH + (ks * 16 + a_kof) * 2;
        ldsm_x4(qfh[ks][0], qfh[ks][1], qfh[ks][2], qfh[ks][3], sbase + AT_STAGE + off);
        ldsm_x4(qfl[ks][0], qfl[ks][1], qfl[ks][2], qfl[ks][3], sbase + AT_STAGE + 18432 + off);
    }
    __syncthreads();

    float O[8][4];
#pragma unroll
    for (int j = 0; j < 8; j++)
#pragma unroll
        for (int r = 0; r < 4; r++) O[j][r] = 0.f;
    float m0 = -1e30f, m1 = -1e30f, l0 = 0.f, l1 = 0.f;

    for (int kt = 0; kt < SS / 64; kt++) {
        const int s = kt & 1;
        if (kt + 1 < SS / 64) { load_kv(s ^ 1, kt + 1); CP_WAIT1(); }
        else                  { CP_WAIT0(); }
        __syncthreads();

        const uint32_t sKh = sbase + s * AT_STAGE;
        const uint32_t sKl = sKh + AT_TILE;
        const uint32_t sVh = sKh + 2 * AT_TILE;
        const uint32_t sVl = sKh + 3 * AT_TILE;

        float sa[8][4];
#pragma unroll
        for (int j = 0; j < 8; j++)
#pragma unroll
            for (int r = 0; r < 4; r++) sa[j][r] = 0.f;
#pragma unroll
        for (int ks = 0; ks < 4; ks++) {
            const uint32_t ko = (uint32_t)(ks * 16 + b_kof) * 2;
            uint32_t kb4[4][4];
#pragma unroll
            for (int p = 0; p < 4; p++)
                ldsm_x4(kb4[p][0], kb4[p][1], kb4[p][2], kb4[p][3],
                        sKh + (uint32_t)(p * 16 + b_nof) * AT_PITCH + ko);
#pragma unroll
            for (int j = 0; j < 8; j++) {
                const int p = j >> 1, hh = j & 1;
                mma16816(sa[j][0], sa[j][1], sa[j][2], sa[j][3],
                         qfh[ks][0], qfh[ks][1], qfh[ks][2], qfh[ks][3],
                         kb4[p][hh * 2], kb4[p][hh * 2 + 1]);
                mma16816(sa[j][0], sa[j][1], sa[j][2], sa[j][3],
                         qfl[ks][0], qfl[ks][1], qfl[ks][2], qfl[ks][3],
                         kb4[p][hh * 2], kb4[p][hh * 2 + 1]);
            }
#pragma unroll
            for (int p = 0; p < 4; p++)
                ldsm_x4(kb4[p][0], kb4[p][1], kb4[p][2], kb4[p][3],
                        sKl + (uint32_t)(p * 16 + b_nof) * AT_PITCH + ko);
#pragma unroll
            for (int j = 0; j < 8; j++) {
                const int p = j >> 1, hh = j & 1;
                mma16816(sa[j][0], sa[j][1], sa[j][2], sa[j][3],
                         qfh[ks][0], qfh[ks][1], qfh[ks][2], qfh[ks][3],
                         kb4[p][hh * 2], kb4[p][hh * 2 + 1]);
            }
        }

        // ---- online softmax
        float tm0 = -1e30f, tm1 = -1e30f;
#pragma unroll
        for (int j = 0; j < 8; j++) {
            tm0 = fmaxf(tm0, fmaxf(sa[j][0], sa[j][1]));
            tm1 = fmaxf(tm1, fmaxf(sa[j][2], sa[j][3]));
        }
        tm0 = fmaxf(tm0, __shfl_xor_sync(0xffffffffu, tm0, 1));
        tm0 = fmaxf(tm0, __shfl_xor_sync(0xffffffffu, tm0, 2));
        tm1 = fmaxf(tm1, __shfl_xor_sync(0xffffffffu, tm1, 1));
        tm1 = fmaxf(tm1, __shfl_xor_sync(0xffffffffu, tm1, 2));
        float mn0 = fmaxf(m0, tm0), mn1 = fmaxf(m1, tm1);
        float al0 = __expf(m0 - mn0), al1 = __expf(m1 - mn1);
        m0 = mn0; m1 = mn1;
        float ls0 = 0.f, ls1 = 0.f;
#pragma unroll
        for (int j = 0; j < 8; j++) {
            sa[j][0] = __expf(sa[j][0] - m0);
            sa[j][1] = __expf(sa[j][1] - m0);
            sa[j][2] = __expf(sa[j][2] - m1);
            sa[j][3] = __expf(sa[j][3] - m1);
            ls0 += sa[j][0] + sa[j][1];
            ls1 += sa[j][2] + sa[j][3];
        }
        ls0 += __shfl_xor_sync(0xffffffffu, ls0, 1);
        ls0 += __shfl_xor_sync(0xffffffffu, ls0, 2);
        ls1 += __shfl_xor_sync(0xffffffffu, ls1, 1);
        ls1 += __shfl_xor_sync(0xffffffffu, ls1, 2);
        l0 = l0 * al0 + ls0;
        l1 = l1 * al1 + ls1;
#pragma unroll
        for (int j = 0; j < 8; j++) {
            O[j][0] *= al0; O[j][1] *= al0;
            O[j][2] *= al1; O[j][3] *= al1;
        }

        // ---- pack P hi/lo
        uint32_t pah[4][4], pal[4][4];
#pragma unroll
        for (int t = 0; t < 4; t++) {
            float e[8] = {sa[2*t][0], sa[2*t][1], sa[2*t][2], sa[2*t][3],
                          sa[2*t+1][0], sa[2*t+1][1], sa[2*t+1][2], sa[2*t+1][3]};
            float hi[8], lo[8];
#pragma unroll
            for (int u = 0; u < 8; u++) {
                hi[u] = __bfloat162float(__float2bfloat16(e[u]));
                lo[u] = e[u] - hi[u];
            }
            pah[t][0] = pack_bf162(hi[0], hi[1]);
            pah[t][1] = pack_bf162(hi[2], hi[3]);
            pah[t][2] = pack_bf162(hi[4], hi[5]);
            pah[t][3] = pack_bf162(hi[6], hi[7]);
            pal[t][0] = pack_bf162(lo[0], lo[1]);
            pal[t][1] = pack_bf162(lo[2], lo[3]);
            pal[t][2] = pack_bf162(lo[4], lo[5]);
            pal[t][3] = pack_bf162(lo[6], lo[7]);
        }

        // ---- O += Ph*Vh + Pl*Vh + Ph*Vl
#pragma unroll
        for (int t = 0; t < 4; t++) {
            const uint32_t ko = (uint32_t)(t * 16 + b_kof) * 2;
            uint32_t vb4[4][4];
#pragma unroll
            for (int p = 0; p < 4; p++)
                ldsm_x4(vb4[p][0], vb4[p][1], vb4[p][2], vb4[p][3],
                        sVh + (uint32_t)(p * 16 + b_nof) * AT_PITCH + ko);
#pragma unroll
            for (int j = 0; j < 8; j++) {
                const int p = j >> 1, hh = j & 1;
                mma16816(O[j][0], O[j][1], O[j][2], O[j][3],
                         pah[t][0], pah[t][1], pah[t][2], pah[t][3],
                         vb4[p][hh * 2], vb4[p][hh * 2 + 1]);
                mma16816(O[j][0], O[j][1], O[j][2], O[j][3],
                         pal[t][0], pal[t][1], pal[t][2], pal[t][3],
                         vb4[p][hh * 2], vb4[p][hh * 2 + 1]);
            }
#pragma unroll
            for (int p = 0; p < 4; p++)
                ldsm_x4(vb4[p][0], vb4[p][1], vb4[p][2], vb4[p][3],
                        sVl + (uint32_t)(p * 16 + b_nof) * AT_PITCH + ko);
#pragma unroll
            for (int j = 0; j < 8; j++) {
                const int p = j >> 1, hh = j & 1;
                mma16816(O[j][0], O[j][1], O[j][2], O[j][3],
                         pah[t][0], pah[t][1], pah[t][2], pah[t][3],
                         vb4[p][hh * 2], vb4[p][hh * 2 + 1]);
            }
        }
        __syncthreads();
    }

    // ---- epilogue: normalize, gate (from fused buffer), write bf16 hi/lo
    float inv0 = 1.f / l0, inv1 = 1.f / l1;
    int r0 = qt * 128 + wid * 16 + (lane >> 2);
    int r1 = r0 + 8;
    const int coff = h * DD + ((lane & 3) << 1);
    size_t gb0 = (size_t)(b * SS + r0) * NQKVG + COL_G + coff;
    size_t gb1 = (size_t)(b * SS + r1) * NQKVG + COL_G + coff;
    size_t ab0 = (size_t)(b * SS + r0) * (NH * DD) + coff;
    size_t ab1 = (size_t)(b * SS + r1) * (NH * DD) + coff;
#pragma unroll
    for (int j = 0; j < 8; j++) {
        float2 gA = *(const float2*)(d_qkvg + gb0 + j * 8);
        float2 gB = *(const float2*)(d_qkvg + gb1 + j * 8);
        float vAx = O[j][0] * inv0 * (1.f / (1.f + __expf(-gA.x)));
        float vAy = O[j][1] * inv0 * (1.f / (1.f + __expf(-gA.y)));
        float vBx = O[j][2] * inv1 * (1.f / (1.f + __expf(-gB.x)));
        float vBy = O[j][3] * inv1 * (1.f / (1.f + __expf(-gB.y)));
        __nv_bfloat16 hAx = __float2bfloat16(vAx), hAy = __float2bfloat16(vAy);
        __nv_bfloat16 hBx = __float2bfloat16(vBx), hBy = __float2bfloat16(vBy);
        *(__nv_bfloat162*)(g_ab_h + ab0 + j * 8) = __nv_bfloat162(hAx, hAy);
        *(__nv_bfloat162*)(g_ab_h + ab1 + j * 8) = __nv_bfloat162(hBx, hBy);
        *(__nv_bfloat162*)(g_ab_l + ab0 + j * 8) = __nv_bfloat162(
            __float2bfloat16(vAx - __bfloat162float(hAx)),
            __float2bfloat16(vAy - __bfloat162float(hAy)));
        *(__nv_bfloat162*)(g_ab_l + ab1 + j * 8) = __nv_bfloat162(
            __float2bfloat16(vBx - __bfloat162float(hBx)),
            __float2bfloat16(vBy - __bfloat162float(hBy)));
    }
}

// ---------------- launch -----------------------------------------------------
extern "C" void kernel_launch(void* const* d_in, const int* in_sizes, int n_in,
                              void* d_out, int out_size)
{
    const float* hs   = (const float*)d_in[0];
    const float* cosb = (const float*)d_in[1];
    const float* sinb = (const float*)d_in[2];
    const float* Wq   = (const float*)d_in[3];
    const float* Wk   = (const float*)d_in[4];
    const float* Wv   = (const float*)d_in[5];
    const float* Wg   = (const float*)d_in[6];
    const float* Wo   = (const float*)d_in[7];
    const float* qg   = (const float*)d_in[8];
    const float* kg   = (const float*)d_in[9];
    float* out = (float*)d_out;

    float* qkvg;
    cudaGetSymbolAddress((void**)&qkvg, d_qkvg);

    __nv_bfloat16 *hs_h, *hs_l, *wqkvg_h, *wqkvg_l, *wo_h, *wo_l, *ab_h, *ab_l;
    __nv_bfloat16 *qh, *ql, *kh, *kl, *vth, *vtl;
    cudaGetSymbolAddress((void**)&hs_h, g_hs_h);
    cudaGetSymbolAddress((void**)&hs_l, g_hs_l);
    cudaGetSymbolAddress((void**)&wqkvg_h, g_wqkvg_h);
    cudaGetSymbolAddress((void**)&wqkvg_l, g_wqkvg_l);
    cudaGetSymbolAddress((void**)&wo_h, g_wo_h);
    cudaGetSymbolAddress((void**)&wo_l, g_wo_l);
    cudaGetSymbolAddress((void**)&ab_h, g_ab_h);
    cudaGetSymbolAddress((void**)&ab_l, g_ab_l);
    cudaGetSymbolAddress((void**)&qh,  g_qh);
    cudaGetSymbolAddress((void**)&ql,  g_ql);
    cudaGetSymbolAddress((void**)&kh,  g_kh);
    cudaGetSymbolAddress((void**)&kl,  g_kl);
    cudaGetSymbolAddress((void**)&vth, g_vth);
    cudaGetSymbolAddress((void**)&vtl, g_vtl);

    cudaFuncSetAttribute(gemm_bf16x3, cudaFuncAttributeMaxDynamicSharedMemorySize, GEMM_SMEM);
    cudaFuncSetAttribute(attn_hmma, cudaFuncAttributeMaxDynamicSharedMemorySize, ATT_SMEM);

    // splits: hs, and the four weights packed into one [4608 x 2048] matrix
    {
        int n4;
        n4 = MROWS * HID / 4;
        split_bf16<<<(n4 + 255) / 256, 256>>>(hs, hs_h, hs_l, n4);
        n4 = HID * HID / 4;   // Wq rows [0,2048)
        split_bf16<<<(n4 + 255) / 256, 256>>>(Wq, wqkvg_h, wqkvg_l, n4);
        n4 = NKV * DD * HID / 4;  // Wk rows [2048,2304)
        split_bf16<<<(n4 + 255) / 256, 256>>>(
            Wk, wqkvg_h + (size_t)COL_K * HID, wqkvg_l + (size_t)COL_K * HID, n4);
        n4 = NKV * DD * HID / 4;  // Wv rows [2304,2560)
        split_bf16<<<(n4 + 255) / 256, 256>>>(
            Wv, wqkvg_h + (size_t)COL_V * HID, wqkvg_l + (size_t)COL_V * HID, n4);
        n4 = HID * HID / 4;   // Wg rows [2560,4608)
        split_bf16<<<(n4 + 255) / 256, 256>>>(
            Wg, wqkvg_h + (size_t)COL_G * HID, wqkvg_l + (size_t)COL_G * HID, n4);
        n4 = HID * HID / 4;
        split_bf16<<<(n4 + 255) / 256, 256>>>(Wo, wo_h, wo_l, n4);
    }

    // fused Q|K|V|G projection via HMMA (one launch, N=4608)
    gemm_bf16x3<<<dim3(NQKVG / 128, MROWS / 128), 256, GEMM_SMEM>>>(
        hs_h, hs_l, wqkvg_h, wqkvg_l, qkvg, MROWS, NQKVG, HID);

    // RMSNorm + RoPE + hi/lo split (Q scaled), V transpose+split
    {
        int rows_q = MROWS * NH;
        int rows_k = MROWS * NKV;
        norm_rope_split<<<(rows_q * 32 + 255) / 256, 256>>>(
            qkvg, cosb, sinb, qg, qh, ql, NH, rows_q, QSCALE, NQKVG, COL_Q);
        norm_rope_split<<<(rows_k * 32 + 255) / 256, 256>>>(
            qkvg, cosb, sinb, kg, kh, kl, NKV, rows_k, 1.0f, NQKVG, COL_K);
        split_v_trans<<<dim3(SS / 64, NKV, BB), 256>>>(qkvg, vth, vtl);
    }

    // attention (+ fused sigmoid gate, writes ab hi/lo directly)
    attn_hmma<<<dim3(SS / 128, NH, BB), 256, ATT_SMEM>>>();

    // output projection
    gemm_bf16x3<<<dim3(HID / 128, MROWS / 128), 256, GEMM_SMEM>>>(
        ab_h, ab_l, wo_h, wo_l, out, MROWS, HID, HID);
}